// round 2
// baseline (speedup 1.0000x reference)
#include <cuda_runtime.h>
#include <math.h>

// Problem constants
#define NB   4
#define NN   4096
#define CF   32
#define NCOL 256          // combined columns: 128 (X, b*32+f) + 128 (H, b*32+f)
#define BPN  (NB*NN)      // 16384 rows of (b,n)

// Scratch (device globals — allocation-free rule)
__device__ float g_R [NN*NCOL];
__device__ float g_T1[NN*NCOL];
__device__ float g_T2[NN*NCOL];
__device__ float g_W [192*128];   // combined gate weights [j=192][c=gate*32+co]
__device__ float g_bias[128];     // bx + bh + b_gate

// ---------------- packed f32x2 helpers ----------------
__device__ __forceinline__ unsigned long long packdup(float x) {
    unsigned long long r;
    unsigned int xi = __float_as_uint(x);
    asm("mov.b64 %0, {%1, %1};" : "=l"(r) : "r"(xi));
    return r;
}
__device__ __forceinline__ void ffma2(unsigned long long& d,
                                      unsigned long long a,
                                      unsigned long long b) {
    asm("fma.rn.f32x2 %0, %1, %2, %3;" : "=l"(d) : "l"(a), "l"(b), "l"(d));
}
__device__ __forceinline__ float2 unpack2(unsigned long long v) {
    float2 r;
    unsigned int lo, hi;
    asm("mov.b64 {%0, %1}, %2;" : "=r"(lo), "=r"(hi) : "l"(v));
    r.x = __uint_as_float(lo);
    r.y = __uint_as_float(hi);
    return r;
}

// ---------------- prep: combine weights & biases ----------------
__global__ void prep_kernel(
    const float* __restrict__ Wxi, const float* __restrict__ Whi,
    const float* __restrict__ Wxf, const float* __restrict__ Whf,
    const float* __restrict__ Wxc, const float* __restrict__ Whc,
    const float* __restrict__ Wxo, const float* __restrict__ Who,
    const float* __restrict__ bxi, const float* __restrict__ bhi,
    const float* __restrict__ bxf, const float* __restrict__ bhf,
    const float* __restrict__ bxc, const float* __restrict__ bhc,
    const float* __restrict__ bxo, const float* __restrict__ bho,
    const float* __restrict__ b_i, const float* __restrict__ b_f,
    const float* __restrict__ b_c, const float* __restrict__ b_o)
{
    const float* Wx[4] = {Wxi, Wxf, Wxc, Wxo};
    const float* Wh[4] = {Whi, Whf, Whc, Who};
    const float* bx[4] = {bxi, bxf, bxc, bxo};
    const float* bh[4] = {bhi, bhf, bhc, bho};
    const float* bg[4] = {b_i, b_f, b_c, b_o};

    for (int idx = threadIdx.x; idx < 192 * 128; idx += blockDim.x) {
        int j = idx >> 7, c = idx & 127;
        int part = j >> 5, r = j & 31;      // part 0..2 = X k0..k2, 3..5 = H k0..k2
        int gate = c >> 5, co = c & 31;
        float v;
        if (part < 3) v = Wx[gate][part * 1024 + r * 32 + co];
        else          v = Wh[gate][(part - 3) * 1024 + r * 32 + co];
        g_W[idx] = v;
    }
    for (int c = threadIdx.x; c < 128; c += blockDim.x) {
        int gate = c >> 5, co = c & 31;
        g_bias[c] = bx[gate][co] + bh[gate][co] + bg[gate][co];
    }
}

// ---------------- pack R = [X | H] into [NN, 256] row-major ----------------
__global__ void pack_kernel(const float* __restrict__ X, const float* __restrict__ H)
{
    int idx = blockIdx.x * blockDim.x + threadIdx.x;   // float4 index, 262144 total
    int m  = idx >> 6;            // row (node)
    int c4 = (idx & 63) << 2;     // column (multiple of 4)
    const float* src;
    if (c4 < 128) {
        int b = c4 >> 5, f = c4 & 31;
        src = X + (b * NN + m) * 32 + f;
    } else {
        int cc = c4 - 128;
        int b = cc >> 5, f = cc & 31;
        src = H + (b * NN + m) * 32 + f;
    }
    ((float4*)g_R)[idx] = *(const float4*)src;
}

// ---------------- GEMM: out[n,c] = alpha * sum_m L[n,m] * B[m,c] (- Sub) ----
#define BM 128
#define BN 64
#define BK 16

__global__ void __launch_bounds__(256)
gemm_kernel(const float* __restrict__ A, int pass)
{
    // pass 0: B=g_R,  C=g_T1,                (T1 = L @ R)
    // pass 1: B=g_T1, C=g_T2, Sub=g_R, x2    (T2 = 2 L @ T1 - R)
    const float* __restrict__ Bm  = pass ? g_T1 : g_R;
    const float* __restrict__ Sub = g_R;
    float* __restrict__ Cm        = pass ? g_T2 : g_T1;

    __shared__ float As[BK][BM];
    __shared__ float Bs[BK][BN];

    int tid = threadIdx.x;
    int tx = tid & 15, ty = tid >> 4;
    int rowBase = blockIdx.y * BM;
    int colBase = blockIdx.x * BN;

    // A tile: 128 rows x 16 cols = 512 float4, 2 per thread
    int aRow0 = tid >> 2;
    int aRow1 = (tid + 256) >> 2;
    int aK0   = (tid & 3) << 2;
    // B tile: 16 rows x 64 cols = 256 float4, 1 per thread
    int bRow = tid >> 4;
    int bC   = (tid & 15) << 2;

    const float* aPtr0 = A + (rowBase + aRow0) * NN + aK0;
    const float* aPtr1 = A + (rowBase + aRow1) * NN + aK0;
    const float* bPtr  = Bm + bRow * NCOL + colBase + bC;

    float4 pa0 = *(const float4*)aPtr0;
    float4 pa1 = *(const float4*)aPtr1;
    float4 pb  = *(const float4*)bPtr;

    unsigned long long acc[4][4];   // [row-pair][col], each packs rows (2rp, 2rp+1)
#pragma unroll
    for (int i = 0; i < 4; i++)
#pragma unroll
        for (int j = 0; j < 4; j++) acc[i][j] = 0ULL;   // (0.0f, 0.0f)

    for (int kt = 0; kt < NN; kt += BK) {
        As[aK0 + 0][aRow0] = pa0.x;
        As[aK0 + 1][aRow0] = pa0.y;
        As[aK0 + 2][aRow0] = pa0.z;
        As[aK0 + 3][aRow0] = pa0.w;
        As[aK0 + 0][aRow1] = pa1.x;
        As[aK0 + 1][aRow1] = pa1.y;
        As[aK0 + 2][aRow1] = pa1.z;
        As[aK0 + 3][aRow1] = pa1.w;
        *(float4*)&Bs[bRow][bC] = pb;
        __syncthreads();

        if (kt + BK < NN) {   // register prefetch of next tiles
            pa0 = *(const float4*)(aPtr0 + kt + BK);
            pa1 = *(const float4*)(aPtr1 + kt + BK);
            pb  = *(const float4*)(bPtr + (kt + BK) * NCOL);
        }

#pragma unroll
        for (int k = 0; k < BK; k++) {
            // rows: reinterpret adjacent fp32 pairs directly as f32x2 (free pack)
            ulonglong2 qa0 = *(const ulonglong2*)&As[k][ty * 8];
            ulonglong2 qa1 = *(const ulonglong2*)&As[k][ty * 8 + 4];
            unsigned long long ap[4] = {qa0.x, qa0.y, qa1.x, qa1.y};
            float4 b = *(const float4*)&Bs[k][tx * 4];
            unsigned long long bb[4];
            bb[0] = packdup(b.x);
            bb[1] = packdup(b.y);
            bb[2] = packdup(b.z);
            bb[3] = packdup(b.w);
#pragma unroll
            for (int rp = 0; rp < 4; rp++) {
#pragma unroll
                for (int c = 0; c < 4; c++) ffma2(acc[rp][c], ap[rp], bb[c]);
            }
        }
        __syncthreads();
    }

    // Epilogue
#pragma unroll
    for (int rp = 0; rp < 4; rp++) {
        int r0 = rowBase + ty * 8 + rp * 2;
        int cb = colBase + tx * 4;
        float2 u0 = unpack2(acc[rp][0]);
        float2 u1 = unpack2(acc[rp][1]);
        float2 u2 = unpack2(acc[rp][2]);
        float2 u3 = unpack2(acc[rp][3]);
        float4 vlo = make_float4(u0.x, u1.x, u2.x, u3.x);
        float4 vhi = make_float4(u0.y, u1.y, u2.y, u3.y);
        if (pass) {
            float4 s0 = *(const float4*)(Sub + r0 * NCOL + cb);
            float4 s1 = *(const float4*)(Sub + (r0 + 1) * NCOL + cb);
            vlo.x = 2.f * vlo.x - s0.x; vlo.y = 2.f * vlo.y - s0.y;
            vlo.z = 2.f * vlo.z - s0.z; vlo.w = 2.f * vlo.w - s0.w;
            vhi.x = 2.f * vhi.x - s1.x; vhi.y = 2.f * vhi.y - s1.y;
            vhi.z = 2.f * vhi.z - s1.z; vhi.w = 2.f * vhi.w - s1.w;
        }
        *(float4*)(Cm + r0 * NCOL + cb)       = vlo;
        *(float4*)(Cm + (r0 + 1) * NCOL + cb) = vhi;
    }
}

// ---------------- gate GEMM + fused LSTM pointwise ----------------
__global__ void __launch_bounds__(128)
gates_kernel(const float* __restrict__ X, const float* __restrict__ H,
             const float* __restrict__ C,
             const float* __restrict__ w_ci, const float* __restrict__ w_cf,
             const float* __restrict__ w_co,
             float* __restrict__ Hout, float* __restrict__ Cout)
{
    __shared__ float sf[16][192];    // features for 16 rows
    __shared__ float pre[16][128];   // gate pre-activations

    int tid  = threadIdx.x;
    int row0 = blockIdx.x * 16;      // flattened (b,n) row base; 16 | 4096 => one b
    int b    = row0 >> 12;
    int n0   = row0 & 4095;

    // Load features: [X | T1x | T2x | H | T1h | T2h] = 192 floats per row
#pragma unroll
    for (int it = 0; it < 6; it++) {
        int i = tid + it * 128;
        int r = i / 48;
        int j = (i % 48) * 4;
        int n = n0 + r;
        const float* src;
        if      (j < 32)  src = X    + (b * NN + n) * 32 + j;
        else if (j < 64)  src = g_T1 + n * NCOL + b * 32 + (j - 32);
        else if (j < 96)  src = g_T2 + n * NCOL + b * 32 + (j - 64);
        else if (j < 128) src = H    + (b * NN + n) * 32 + (j - 96);
        else if (j < 160) src = g_T1 + n * NCOL + 128 + b * 32 + (j - 128);
        else              src = g_T2 + n * NCOL + 128 + b * 32 + (j - 160);
        *(float4*)&sf[r][j] = *(const float4*)src;
    }
    __syncthreads();

    int c = tid;                     // output column 0..127 (gate*32 + co)
    float acc[16];
#pragma unroll
    for (int r = 0; r < 16; r++) acc[r] = 0.f;

#pragma unroll 4
    for (int q = 0; q < 48; q++) {
        int j = q * 4;
        float w0 = g_W[(j + 0) * 128 + c];
        float w1 = g_W[(j + 1) * 128 + c];
        float w2 = g_W[(j + 2) * 128 + c];
        float w3 = g_W[(j + 3) * 128 + c];
#pragma unroll
        for (int r = 0; r < 16; r++) {
            float4 f = *(const float4*)&sf[r][j];
            acc[r] = fmaf(f.x, w0, fmaf(f.y, w1, fmaf(f.z, w2, fmaf(f.w, w3, acc[r]))));
        }
    }
    float bias = g_bias[c];
#pragma unroll
    for (int r = 0; r < 16; r++) pre[r][c] = acc[r] + bias;
    __syncthreads();

    // Pointwise LSTM: 16 rows x 32 features = 512 outputs, 4 per thread
#pragma unroll
    for (int q = 0; q < 4; q++) {
        int item = tid + q * 128;
        int r = item >> 5, f = item & 31;
        int n = n0 + r;
        int gidx = (b * NN + n) * 32 + f;
        float cv = C[gidx];
        float pi = pre[r][f];
        float pf = pre[r][32 + f];
        float pc = pre[r][64 + f];
        float po = pre[r][96 + f];
        float I  = 1.f / (1.f + expf(-(pi + w_ci[f] * cv)));
        float F  = 1.f / (1.f + expf(-(pf + w_cf[f] * cv)));
        float T  = tanhf(pc);
        float cn = F * cv + I * T;
        float O  = 1.f / (1.f + expf(-(po + w_co[f] * cn)));
        Hout[gidx] = O * tanhf(cn);
        Cout[gidx] = cn;
    }
}

// ---------------- launch ----------------
extern "C" void kernel_launch(void* const* d_in, const int* in_sizes, int n_in,
                              void* d_out, int out_size)
{
    const float* X   = (const float*)d_in[0];
    const float* L   = (const float*)d_in[1];
    const float* H   = (const float*)d_in[2];
    const float* C   = (const float*)d_in[3];
    const float* Wxi = (const float*)d_in[4];
    const float* bxi = (const float*)d_in[5];
    const float* Whi = (const float*)d_in[6];
    const float* bhi = (const float*)d_in[7];
    const float* Wxf = (const float*)d_in[8];
    const float* bxf = (const float*)d_in[9];
    const float* Whf = (const float*)d_in[10];
    const float* bhf = (const float*)d_in[11];
    const float* Wxc = (const float*)d_in[12];
    const float* bxc = (const float*)d_in[13];
    const float* Whc = (const float*)d_in[14];
    const float* bhc = (const float*)d_in[15];
    const float* Wxo = (const float*)d_in[16];
    const float* bxo = (const float*)d_in[17];
    const float* Who = (const float*)d_in[18];
    const float* bho = (const float*)d_in[19];
    const float* w_ci = (const float*)d_in[20];
    const float* w_cf = (const float*)d_in[21];
    const float* w_co = (const float*)d_in[22];
    const float* b_i = (const float*)d_in[23];
    const float* b_f = (const float*)d_in[24];
    const float* b_c = (const float*)d_in[25];
    const float* b_o = (const float*)d_in[26];

    float* Hout = (float*)d_out;
    float* Cout = Hout + NB * NN * CF;

    prep_kernel<<<1, 256>>>(Wxi, Whi, Wxf, Whf, Wxc, Whc, Wxo, Who,
                            bxi, bhi, bxf, bhf, bxc, bhc, bxo, bho,
                            b_i, b_f, b_c, b_o);
    pack_kernel<<<(NN * NCOL / 4) / 256, 256>>>(X, H);

    dim3 ggrid(NCOL / BN, NN / BM);   // (4, 32) = 128 blocks
    gemm_kernel<<<ggrid, 256>>>(L, 0);
    gemm_kernel<<<ggrid, 256>>>(L, 1);

    gates_kernel<<<BPN / 16, 128>>>(X, H, C, w_ci, w_cf, w_co, Hout, Cout);
}

// round 4
// speedup vs baseline: 1.0174x; 1.0174x over previous
#include <cuda_runtime.h>
#include <math.h>

// Problem constants
#define NB   4
#define NN   4096
#define CF   32
#define NCOL 256          // combined columns: 128 (X, b*32+f) + 128 (H, b*32+f)
#define BPN  (NB*NN)      // 16384 rows of (b,n)

// Scratch (device globals — allocation-free rule)
__device__ float g_R [NN*NCOL];
__device__ float g_T1[NN*NCOL];
__device__ float g_T2[NN*NCOL];
__device__ float g_W [192*128];   // combined gate weights [j=192][c=gate*32+co]
__device__ float g_bias[128];     // bx + bh + b_gate

// ---------------- packed f32x2 helpers ----------------
__device__ __forceinline__ unsigned long long packdup(float x) {
    unsigned long long r;
    unsigned int xi = __float_as_uint(x);
    asm("mov.b64 %0, {%1, %1};" : "=l"(r) : "r"(xi));
    return r;
}
__device__ __forceinline__ void ffma2(unsigned long long& d,
                                      unsigned long long a,
                                      unsigned long long b) {
    asm("fma.rn.f32x2 %0, %1, %2, %3;" : "=l"(d) : "l"(a), "l"(b), "l"(d));
}
__device__ __forceinline__ float2 unpack2(unsigned long long v) {
    float2 r;
    unsigned int lo, hi;
    asm("mov.b64 {%0, %1}, %2;" : "=r"(lo), "=r"(hi) : "l"(v));
    r.x = __uint_as_float(lo);
    r.y = __uint_as_float(hi);
    return r;
}

// ---------------- prep: combine weights & biases ----------------
__global__ void prep_kernel(
    const float* __restrict__ Wxi, const float* __restrict__ Whi,
    const float* __restrict__ Wxf, const float* __restrict__ Whf,
    const float* __restrict__ Wxc, const float* __restrict__ Whc,
    const float* __restrict__ Wxo, const float* __restrict__ Who,
    const float* __restrict__ bxi, const float* __restrict__ bhi,
    const float* __restrict__ bxf, const float* __restrict__ bhf,
    const float* __restrict__ bxc, const float* __restrict__ bhc,
    const float* __restrict__ bxo, const float* __restrict__ bho,
    const float* __restrict__ b_i, const float* __restrict__ b_f,
    const float* __restrict__ b_c, const float* __restrict__ b_o)
{
    const float* Wx[4] = {Wxi, Wxf, Wxc, Wxo};
    const float* Wh[4] = {Whi, Whf, Whc, Who};
    const float* bx[4] = {bxi, bxf, bxc, bxo};
    const float* bh[4] = {bhi, bhf, bhc, bho};
    const float* bg[4] = {b_i, b_f, b_c, b_o};

    for (int idx = threadIdx.x; idx < 192 * 128; idx += blockDim.x) {
        int j = idx >> 7, c = idx & 127;
        int part = j >> 5, r = j & 31;      // part 0..2 = X k0..k2, 3..5 = H k0..k2
        int gate = c >> 5, co = c & 31;
        float v;
        if (part < 3) v = Wx[gate][part * 1024 + r * 32 + co];
        else          v = Wh[gate][(part - 3) * 1024 + r * 32 + co];
        g_W[idx] = v;
    }
    for (int c = threadIdx.x; c < 128; c += blockDim.x) {
        int gate = c >> 5, co = c & 31;
        g_bias[c] = bx[gate][co] + bh[gate][co] + bg[gate][co];
    }
}

// ---------------- pack R = [X | H] into [NN, 256] row-major ----------------
__global__ void pack_kernel(const float* __restrict__ X, const float* __restrict__ H)
{
    int idx = blockIdx.x * blockDim.x + threadIdx.x;   // float4 index, 262144 total
    int m  = idx >> 6;            // row (node)
    int c4 = (idx & 63) << 2;     // column (multiple of 4)
    const float* src;
    if (c4 < 128) {
        int b = c4 >> 5, f = c4 & 31;
        src = X + (b * NN + m) * 32 + f;
    } else {
        int cc = c4 - 128;
        int b = cc >> 5, f = cc & 31;
        src = H + (b * NN + m) * 32 + f;
    }
    ((float4*)g_R)[idx] = *(const float4*)src;
}

// ---------------- GEMM: out[n,c] = alpha * sum_m L[n,m] * B[m,c] (- Sub) ----
#define BM 128
#define BN 64
#define BK 16

__global__ void __launch_bounds__(256)
gemm_kernel(const float* __restrict__ A, int pass)
{
    // pass 0: B=g_R,  C=g_T1,                (T1 = L @ R)
    // pass 1: B=g_T1, C=g_T2, Sub=g_R, x2    (T2 = 2 L @ T1 - R)
    const float* __restrict__ Bm  = pass ? g_T1 : g_R;
    const float* __restrict__ Sub = g_R;
    float* __restrict__ Cm        = pass ? g_T2 : g_T1;

    __shared__ float As[BK][BM];
    __shared__ float Bs[BK][BN];

    int tid = threadIdx.x;
    int tx = tid & 15, ty = tid >> 4;
    int rowBase = blockIdx.y * BM;
    int colBase = blockIdx.x * BN;

    // A tile: 128 rows x 16 cols = 512 float4, 2 per thread
    int aRow0 = tid >> 2;
    int aRow1 = (tid + 256) >> 2;
    int aK0   = (tid & 3) << 2;
    // B tile: 16 rows x 64 cols = 256 float4, 1 per thread
    int bRow = tid >> 4;
    int bC   = (tid & 15) << 2;

    const float* aPtr0 = A + (rowBase + aRow0) * NN + aK0;
    const float* aPtr1 = A + (rowBase + aRow1) * NN + aK0;
    const float* bPtr  = Bm + bRow * NCOL + colBase + bC;

    float4 pa0 = *(const float4*)aPtr0;
    float4 pa1 = *(const float4*)aPtr1;
    float4 pb  = *(const float4*)bPtr;

    unsigned long long acc[4][4];   // [row-pair][col], each packs rows (2rp, 2rp+1)
#pragma unroll
    for (int i = 0; i < 4; i++)
#pragma unroll
        for (int j = 0; j < 4; j++) acc[i][j] = 0ULL;   // (0.0f, 0.0f)

    for (int kt = 0; kt < NN; kt += BK) {
        As[aK0 + 0][aRow0] = pa0.x;
        As[aK0 + 1][aRow0] = pa0.y;
        As[aK0 + 2][aRow0] = pa0.z;
        As[aK0 + 3][aRow0] = pa0.w;
        As[aK0 + 0][aRow1] = pa1.x;
        As[aK0 + 1][aRow1] = pa1.y;
        As[aK0 + 2][aRow1] = pa1.z;
        As[aK0 + 3][aRow1] = pa1.w;
        *(float4*)&Bs[bRow][bC] = pb;
        __syncthreads();

        if (kt + BK < NN) {   // register prefetch of next tiles
            pa0 = *(const float4*)(aPtr0 + kt + BK);
            pa1 = *(const float4*)(aPtr1 + kt + BK);
            pb  = *(const float4*)(bPtr + (kt + BK) * NCOL);
        }

#pragma unroll
        for (int k = 0; k < BK; k++) {
            // rows: reinterpret adjacent fp32 pairs directly as f32x2 (free pack)
            ulonglong2 qa0 = *(const ulonglong2*)&As[k][ty * 8];
            ulonglong2 qa1 = *(const ulonglong2*)&As[k][ty * 8 + 4];
            unsigned long long ap[4] = {qa0.x, qa0.y, qa1.x, qa1.y};
            float4 b = *(const float4*)&Bs[k][tx * 4];
            unsigned long long bb[4];
            bb[0] = packdup(b.x);
            bb[1] = packdup(b.y);
            bb[2] = packdup(b.z);
            bb[3] = packdup(b.w);
#pragma unroll
            for (int rp = 0; rp < 4; rp++) {
#pragma unroll
                for (int c = 0; c < 4; c++) ffma2(acc[rp][c], ap[rp], bb[c]);
            }
        }
        __syncthreads();
    }

    // Epilogue
#pragma unroll
    for (int rp = 0; rp < 4; rp++) {
        int r0 = rowBase + ty * 8 + rp * 2;
        int cb = colBase + tx * 4;
        float2 u0 = unpack2(acc[rp][0]);
        float2 u1 = unpack2(acc[rp][1]);
        float2 u2 = unpack2(acc[rp][2]);
        float2 u3 = unpack2(acc[rp][3]);
        float4 vlo = make_float4(u0.x, u1.x, u2.x, u3.x);
        float4 vhi = make_float4(u0.y, u1.y, u2.y, u3.y);
        if (pass) {
            float4 s0 = *(const float4*)(Sub + r0 * NCOL + cb);
            float4 s1 = *(const float4*)(Sub + (r0 + 1) * NCOL + cb);
            vlo.x = 2.f * vlo.x - s0.x; vlo.y = 2.f * vlo.y - s0.y;
            vlo.z = 2.f * vlo.z - s0.z; vlo.w = 2.f * vlo.w - s0.w;
            vhi.x = 2.f * vhi.x - s1.x; vhi.y = 2.f * vhi.y - s1.y;
            vhi.z = 2.f * vhi.z - s1.z; vhi.w = 2.f * vhi.w - s1.w;
        }
        *(float4*)(Cm + r0 * NCOL + cb)       = vlo;
        *(float4*)(Cm + (r0 + 1) * NCOL + cb) = vhi;
    }
}

// ---------------- gate GEMM + fused LSTM pointwise ----------------
__global__ void __launch_bounds__(128)
gates_kernel(const float* __restrict__ X, const float* __restrict__ H,
             const float* __restrict__ C,
             const float* __restrict__ w_ci, const float* __restrict__ w_cf,
             const float* __restrict__ w_co,
             float* __restrict__ Hout, float* __restrict__ Cout)
{
    __shared__ float sf[16][192];    // features for 16 rows
    __shared__ float pre[16][128];   // gate pre-activations

    int tid  = threadIdx.x;
    int row0 = blockIdx.x * 16;      // flattened (b,n) row base; 16 | 4096 => one b
    int b    = row0 >> 12;
    int n0   = row0 & 4095;

    // Load features: [X | T1x | T2x | H | T1h | T2h] = 192 floats per row
#pragma unroll
    for (int it = 0; it < 6; it++) {
        int i = tid + it * 128;
        int r = i / 48;
        int j = (i % 48) * 4;
        int n = n0 + r;
        const float* src;
        if      (j < 32)  src = X    + (b * NN + n) * 32 + j;
        else if (j < 64)  src = g_T1 + n * NCOL + b * 32 + (j - 32);
        else if (j < 96)  src = g_T2 + n * NCOL + b * 32 + (j - 64);
        else if (j < 128) src = H    + (b * NN + n) * 32 + (j - 96);
        else if (j < 160) src = g_T1 + n * NCOL + 128 + b * 32 + (j - 128);
        else              src = g_T2 + n * NCOL + 128 + b * 32 + (j - 160);
        *(float4*)&sf[r][j] = *(const float4*)src;
    }
    __syncthreads();

    int c = tid;                     // output column 0..127 (gate*32 + co)
    float acc[16];
#pragma unroll
    for (int r = 0; r < 16; r++) acc[r] = 0.f;

#pragma unroll 4
    for (int q = 0; q < 48; q++) {
        int j = q * 4;
        float w0 = g_W[(j + 0) * 128 + c];
        float w1 = g_W[(j + 1) * 128 + c];
        float w2 = g_W[(j + 2) * 128 + c];
        float w3 = g_W[(j + 3) * 128 + c];
#pragma unroll
        for (int r = 0; r < 16; r++) {
            float4 f = *(const float4*)&sf[r][j];
            acc[r] = fmaf(f.x, w0, fmaf(f.y, w1, fmaf(f.z, w2, fmaf(f.w, w3, acc[r]))));
        }
    }
    float bias = g_bias[c];
#pragma unroll
    for (int r = 0; r < 16; r++) pre[r][c] = acc[r] + bias;
    __syncthreads();

    // Pointwise LSTM: 16 rows x 32 features = 512 outputs, 4 per thread
#pragma unroll
    for (int q = 0; q < 4; q++) {
        int item = tid + q * 128;
        int r = item >> 5, f = item & 31;
        int n = n0 + r;
        int gidx = (b * NN + n) * 32 + f;
        float cv = C[gidx];
        float pi = pre[r][f];
        float pf = pre[r][32 + f];
        float pc = pre[r][64 + f];
        float po = pre[r][96 + f];
        float I  = 1.f / (1.f + expf(-(pi + w_ci[f] * cv)));
        float F  = 1.f / (1.f + expf(-(pf + w_cf[f] * cv)));
        float T  = tanhf(pc);
        float cn = F * cv + I * T;
        float O  = 1.f / (1.f + expf(-(po + w_co[f] * cn)));
        Hout[gidx] = O * tanhf(cn);
        Cout[gidx] = cn;
    }
}

// ---------------- launch ----------------
extern "C" void kernel_launch(void* const* d_in, const int* in_sizes, int n_in,
                              void* d_out, int out_size)
{
    const float* X   = (const float*)d_in[0];
    const float* L   = (const float*)d_in[1];
    const float* H   = (const float*)d_in[2];
    const float* C   = (const float*)d_in[3];
    const float* Wxi = (const float*)d_in[4];
    const float* bxi = (const float*)d_in[5];
    const float* Whi = (const float*)d_in[6];
    const float* bhi = (const float*)d_in[7];
    const float* Wxf = (const float*)d_in[8];
    const float* bxf = (const float*)d_in[9];
    const float* Whf = (const float*)d_in[10];
    const float* bhf = (const float*)d_in[11];
    const float* Wxc = (const float*)d_in[12];
    const float* bxc = (const float*)d_in[13];
    const float* Whc = (const float*)d_in[14];
    const float* bhc = (const float*)d_in[15];
    const float* Wxo = (const float*)d_in[16];
    const float* bxo = (const float*)d_in[17];
    const float* Who = (const float*)d_in[18];
    const float* bho = (const float*)d_in[19];
    const float* w_ci = (const float*)d_in[20];
    const float* w_cf = (const float*)d_in[21];
    const float* w_co = (const float*)d_in[22];
    const float* b_i = (const float*)d_in[23];
    const float* b_f = (const float*)d_in[24];
    const float* b_c = (const float*)d_in[25];
    const float* b_o = (const float*)d_in[26];

    float* Hout = (float*)d_out;
    float* Cout = Hout + NB * NN * CF;

    prep_kernel<<<1, 256>>>(Wxi, Whi, Wxf, Whf, Wxc, Whc, Wxo, Who,
                            bxi, bhi, bxf, bhf, bxc, bhc, bxo, bho,
                            b_i, b_f, b_c, b_o);
    pack_kernel<<<(NN * NCOL / 4) / 256, 256>>>(X, H);

    dim3 ggrid(NCOL / BN, NN / BM);   // (4, 32) = 128 blocks
    gemm_kernel<<<ggrid, 256>>>(L, 0);
    gemm_kernel<<<ggrid, 256>>>(L, 1);

    gates_kernel<<<BPN / 16, 128>>>(X, H, C, w_ci, w_cf, w_co, Hout, Cout);
}

// round 8
// speedup vs baseline: 2.1393x; 2.1027x over previous
#include <cuda_runtime.h>
#include <cuda_bf16.h>
#include <cstdint>
#include <math.h>

// Problem constants
#define NB   4
#define NN   4096
#define CF   32
#define NCOL 256          // combined columns: 128 (X) + 128 (H), each b*32+f
#define BPN  (NB*NN)

// GEMM tiling
#define GM 128
#define GN 64
#define KC 64              // bf16 k-elements per chunk (128 B per row)
#define NCHUNK (NN / KC)   // 64
#define STAGES 3
#define A_TILE 16384       // 128 rows * 128 B
#define B_TILE 8192        // 64 rows * 128 B
#define STAGE_BYTES (2*A_TILE + 2*B_TILE)          // 49152
#define GEMM_SMEM (STAGES * STAGE_BYTES)           // 147456

#define SWZ(x) ((x) ^ (((x) >> 3) & 0x70))

// ---------------- device scratch (allocation-free rule) ----------------
__device__ __nv_bfloat16 g_Lhi[(size_t)NN*NN];
__device__ __nv_bfloat16 g_Llo[(size_t)NN*NN];
__device__ __nv_bfloat16 g_Bhi[(size_t)NN*NCOL];   // B operand split, [m][c] layout
__device__ __nv_bfloat16 g_Blo[(size_t)NN*NCOL];
__device__ float g_Rf [NN*NCOL];
__device__ float g_T1f[NN*NCOL];
__device__ float g_T2f[NN*NCOL];
__device__ float g_W [192*128];
__device__ float g_bias[128];

// ---------------- low-level helpers ----------------
__device__ __forceinline__ uint32_t smem_u32(const void* p) {
    uint32_t a;
    asm("{ .reg .u64 t; cvta.to.shared.u64 t, %1; cvt.u32.u64 %0, t; }" : "=r"(a) : "l"(p));
    return a;
}
__device__ __forceinline__ void cp_async16(uint32_t saddr, const void* gptr) {
    asm volatile("cp.async.cg.shared.global [%0], [%1], 16;" :: "r"(saddr), "l"(gptr));
}
__device__ __forceinline__ void cp_commit() {
    asm volatile("cp.async.commit_group;" ::: "memory");
}

#define LDSM4(r, a) \
    asm volatile("ldmatrix.sync.aligned.m8n8.x4.shared.b16 {%0,%1,%2,%3}, [%4];" \
        : "=r"((r)[0]), "=r"((r)[1]), "=r"((r)[2]), "=r"((r)[3]) : "r"(a))
#define LDSM4T(r, a) \
    asm volatile("ldmatrix.sync.aligned.m8n8.x4.trans.shared.b16 {%0,%1,%2,%3}, [%4];" \
        : "=r"((r)[0]), "=r"((r)[1]), "=r"((r)[2]), "=r"((r)[3]) : "r"(a))
#define MMA(c, a, b) \
    asm volatile("mma.sync.aligned.m16n8k16.row.col.f32.bf16.bf16.f32 " \
        "{%0,%1,%2,%3}, {%4,%5,%6,%7}, {%8,%9}, {%0,%1,%2,%3};" \
        : "+f"((c)[0]), "+f"((c)[1]), "+f"((c)[2]), "+f"((c)[3]) \
        : "r"((a)[0]), "r"((a)[1]), "r"((a)[2]), "r"((a)[3]), \
          "r"((b)[0]), "r"((b)[1]))

// ---------------- prep: combine weights & biases ----------------
__global__ void prep_kernel(
    const float* __restrict__ Wxi, const float* __restrict__ Whi,
    const float* __restrict__ Wxf, const float* __restrict__ Whf,
    const float* __restrict__ Wxc, const float* __restrict__ Whc,
    const float* __restrict__ Wxo, const float* __restrict__ Who,
    const float* __restrict__ bxi, const float* __restrict__ bhi,
    const float* __restrict__ bxf, const float* __restrict__ bhf,
    const float* __restrict__ bxc, const float* __restrict__ bhc,
    const float* __restrict__ bxo, const float* __restrict__ bho,
    const float* __restrict__ b_i, const float* __restrict__ b_f,
    const float* __restrict__ b_c, const float* __restrict__ b_o)
{
    const float* Wx[4] = {Wxi, Wxf, Wxc, Wxo};
    const float* Wh[4] = {Whi, Whf, Whc, Who};
    const float* bx[4] = {bxi, bxf, bxc, bxo};
    const float* bh[4] = {bhi, bhf, bhc, bho};
    const float* bg[4] = {b_i, b_f, b_c, b_o};

    for (int idx = threadIdx.x; idx < 192 * 128; idx += blockDim.x) {
        int j = idx >> 7, c = idx & 127;
        int part = j >> 5, r = j & 31;
        int gate = c >> 5, co = c & 31;
        float v;
        if (part < 3) v = Wx[gate][part * 1024 + r * 32 + co];
        else          v = Wh[gate][(part - 3) * 1024 + r * 32 + co];
        g_W[idx] = v;
    }
    for (int c = threadIdx.x; c < 128; c += blockDim.x) {
        int gate = c >> 5, co = c & 31;
        g_bias[c] = bx[gate][co] + bh[gate][co] + bg[gate][co];
    }
}

// ---------------- split L (fp32 -> bf16 hi/lo) ----------------
__global__ void __launch_bounds__(256)
splitL_kernel(const float4* __restrict__ L4)
{
    int idx = blockIdx.x * blockDim.x + threadIdx.x;
    float4 v = L4[idx];
    __nv_bfloat16 h0 = __float2bfloat16(v.x);
    __nv_bfloat16 h1 = __float2bfloat16(v.y);
    __nv_bfloat16 h2 = __float2bfloat16(v.z);
    __nv_bfloat16 h3 = __float2bfloat16(v.w);
    __nv_bfloat16 l0 = __float2bfloat16(v.x - __bfloat162float(h0));
    __nv_bfloat16 l1 = __float2bfloat16(v.y - __bfloat162float(h1));
    __nv_bfloat16 l2 = __float2bfloat16(v.z - __bfloat162float(h2));
    __nv_bfloat16 l3 = __float2bfloat16(v.w - __bfloat162float(h3));
    __nv_bfloat162* H2 = (__nv_bfloat162*)g_Lhi;
    __nv_bfloat162* L2 = (__nv_bfloat162*)g_Llo;
    H2[2*idx]   = __halves2bfloat162(h0, h1);
    H2[2*idx+1] = __halves2bfloat162(h2, h3);
    L2[2*idx]   = __halves2bfloat162(l0, l1);
    L2[2*idx+1] = __halves2bfloat162(l2, l3);
}

// ---------------- split B operand (fp32 [4096][256] -> bf16 hi/lo) -------
__global__ void __launch_bounds__(256)
splitB_kernel(int which)    // 0: src = g_Rf, 1: src = g_T1f
{
    int idx = blockIdx.x * blockDim.x + threadIdx.x;   // float4 index
    const float4* src = (const float4*)(which ? g_T1f : g_Rf);
    float4 v = src[idx];
    __nv_bfloat16 h0 = __float2bfloat16(v.x);
    __nv_bfloat16 h1 = __float2bfloat16(v.y);
    __nv_bfloat16 h2 = __float2bfloat16(v.z);
    __nv_bfloat16 h3 = __float2bfloat16(v.w);
    __nv_bfloat16 l0 = __float2bfloat16(v.x - __bfloat162float(h0));
    __nv_bfloat16 l1 = __float2bfloat16(v.y - __bfloat162float(h1));
    __nv_bfloat16 l2 = __float2bfloat16(v.z - __bfloat162float(h2));
    __nv_bfloat16 l3 = __float2bfloat16(v.w - __bfloat162float(h3));
    __nv_bfloat162* H2 = (__nv_bfloat162*)g_Bhi;
    __nv_bfloat162* L2 = (__nv_bfloat162*)g_Blo;
    H2[2*idx]   = __halves2bfloat162(h0, h1);
    H2[2*idx+1] = __halves2bfloat162(h2, h3);
    L2[2*idx]   = __halves2bfloat162(l0, l1);
    L2[2*idx+1] = __halves2bfloat162(l2, l3);
}

// ---------------- pack R = [X | H] into fp32 [NN, 256] ----------------
__global__ void pack_kernel(const float* __restrict__ X, const float* __restrict__ H)
{
    int idx = blockIdx.x * blockDim.x + threadIdx.x;   // float4 index
    int m  = idx >> 6;
    int c4 = (idx & 63) << 2;
    const float* src;
    if (c4 < 128) {
        int b = c4 >> 5, f = c4 & 31;
        src = X + (b * NN + m) * 32 + f;
    } else {
        int cc = c4 - 128;
        int b = cc >> 5, f = cc & 31;
        src = H + (b * NN + m) * 32 + f;
    }
    ((float4*)g_Rf)[idx] = *(const float4*)src;
}

// ---------------- HMMA GEMM: D = L @ B (3-product bf16 split) ------------
__device__ __forceinline__ void issue_stage(uint32_t stb, int ck, int rowBase,
                                            int colBase, int tid)
{
    const char* Lh = (const char*)g_Lhi;
    const char* Ll = (const char*)g_Llo;
    const char* Bh = (const char*)g_Bhi;
    const char* Bl = (const char*)g_Blo;
    size_t ka = (size_t)ck * 128;              // byte offset along K in L rows
#pragma unroll
    for (int i = 0; i < 4; i++) {
        int g = tid + i * 256;
        int r = g >> 3, cb = (g & 7) << 4;     // A: 128 rows x 8x16B
        uint32_t d = SWZ((uint32_t)(r * 128 + cb));
        size_t so = (size_t)(rowBase + r) * 8192 + ka + cb;
        cp_async16(stb + d,          Lh + so);
        cp_async16(stb + A_TILE + d, Ll + so);
    }
#pragma unroll
    for (int i = 0; i < 2; i++) {
        int g = tid + i * 256;
        int r = g >> 3, cb = (g & 7) << 4;     // B: 64 k-rows x 8x16B
        uint32_t d = SWZ((uint32_t)(r * 128 + cb));
        size_t so = (size_t)(ck * KC + r) * 512 + (size_t)colBase * 2 + cb;
        cp_async16(stb + 2*A_TILE + d,          Bh + so);
        cp_async16(stb + 2*A_TILE + B_TILE + d, Bl + so);
    }
}

__global__ void __launch_bounds__(256, 1)
mma_gemm(int pass)
{
    extern __shared__ __align__(1024) char smem[];
    uint32_t sb = smem_u32(smem);
    int tid  = threadIdx.x;
    int lane = tid & 31, wid = tid >> 5;
    int wm = wid & 3;          // M quadrant (rows wm*32)
    int wn = wid >> 2;         // N half (cols wn*32)
    int rowBase = blockIdx.y * GM;
    int colBase = blockIdx.x * GN;

    int laneRow  = lane & 15;
    int laneHalf = (lane >> 4) << 4;

    float acc[2][4][4];
#pragma unroll
    for (int a = 0; a < 2; a++)
#pragma unroll
        for (int b = 0; b < 4; b++)
#pragma unroll
            for (int c = 0; c < 4; c++) acc[a][b][c] = 0.f;

    // prologue: stages 0, 1
    issue_stage(sb + 0 * STAGE_BYTES, 0, rowBase, colBase, tid);
    cp_commit();
    issue_stage(sb + 1 * STAGE_BYTES, 1, rowBase, colBase, tid);
    cp_commit();

    for (int ck = 0; ck < NCHUNK; ck++) {
        asm volatile("cp.async.wait_group 1;" ::: "memory");
        __syncthreads();

        if (ck + 2 < NCHUNK)
            issue_stage(sb + ((ck + 2) % STAGES) * STAGE_BYTES, ck + 2,
                        rowBase, colBase, tid);
        cp_commit();   // empty group in tail keeps wait_group accounting exact

        uint32_t stb = sb + (ck % STAGES) * STAGE_BYTES;
#pragma unroll
        for (int ks = 0; ks < 4; ks++) {
            uint32_t ah[2][4], al[2][4];
#pragma unroll
            for (int mt = 0; mt < 2; mt++) {
                uint32_t off = SWZ((uint32_t)((wm * 32 + mt * 16 + laneRow) * 128
                                              + ks * 32 + laneHalf));
                LDSM4(ah[mt], stb + off);
                LDSM4(al[mt], stb + A_TILE + off);
            }
            uint32_t bh[4][2], bl[4][2];
#pragma unroll
            for (int nh = 0; nh < 2; nh++) {
                uint32_t off = SWZ((uint32_t)((ks * 16 + laneRow) * 128
                                              + wn * 64 + nh * 32 + laneHalf));
                uint32_t q[4];
                LDSM4T(q, stb + 2*A_TILE + off);
                bh[nh*2][0] = q[0]; bh[nh*2][1] = q[1];
                bh[nh*2+1][0] = q[2]; bh[nh*2+1][1] = q[3];
                LDSM4T(q, stb + 2*A_TILE + B_TILE + off);
                bl[nh*2][0] = q[0]; bl[nh*2][1] = q[1];
                bl[nh*2+1][0] = q[2]; bl[nh*2+1][1] = q[3];
            }
#pragma unroll
            for (int mt = 0; mt < 2; mt++)
#pragma unroll
                for (int nt = 0; nt < 4; nt++) {
                    MMA(acc[mt][nt], ah[mt], bh[nt]);
                    MMA(acc[mt][nt], ah[mt], bl[nt]);
                    MMA(acc[mt][nt], al[mt], bh[nt]);
                }
        }
        __syncthreads();
    }

    // epilogue
    float* dst = pass ? g_T2f : g_T1f;
    int r0 = rowBase + wm * 32 + (lane >> 2);
    int c0 = colBase + wn * 32 + ((lane & 3) << 1);
#pragma unroll
    for (int mt = 0; mt < 2; mt++) {
#pragma unroll
        for (int nt = 0; nt < 4; nt++) {
            int rr = r0 + mt * 16;
            int cc = c0 + nt * 8;
            float2 vlo = make_float2(acc[mt][nt][0], acc[mt][nt][1]);
            float2 vhi = make_float2(acc[mt][nt][2], acc[mt][nt][3]);
            if (pass) {
                float2 s0 = *(const float2*)(g_Rf + (size_t)rr * NCOL + cc);
                float2 s1 = *(const float2*)(g_Rf + (size_t)(rr + 8) * NCOL + cc);
                vlo.x = 2.f * vlo.x - s0.x;  vlo.y = 2.f * vlo.y - s0.y;
                vhi.x = 2.f * vhi.x - s1.x;  vhi.y = 2.f * vhi.y - s1.y;
            }
            *(float2*)(dst + (size_t)rr * NCOL + cc)       = vlo;
            *(float2*)(dst + (size_t)(rr + 8) * NCOL + cc) = vhi;
        }
    }
}

// ---------------- gate GEMM + fused LSTM pointwise ----------------
__global__ void __launch_bounds__(128)
gates_kernel(const float* __restrict__ X, const float* __restrict__ H,
             const float* __restrict__ C,
             const float* __restrict__ w_ci, const float* __restrict__ w_cf,
             const float* __restrict__ w_co,
             float* __restrict__ Hout, float* __restrict__ Cout)
{
    __shared__ float sf[16][192];
    __shared__ float pre[16][128];

    int tid  = threadIdx.x;
    int row0 = blockIdx.x * 16;
    int b    = row0 >> 12;
    int n0   = row0 & 4095;

#pragma unroll
    for (int it = 0; it < 6; it++) {
        int i = tid + it * 128;
        int r = i / 48;
        int j = (i % 48) * 4;
        int n = n0 + r;
        const float* src;
        if      (j < 32)  src = X     + (b * NN + n) * 32 + j;
        else if (j < 64)  src = g_T1f + n * NCOL + b * 32 + (j - 32);
        else if (j < 96)  src = g_T2f + n * NCOL + b * 32 + (j - 64);
        else if (j < 128) src = H     + (b * NN + n) * 32 + (j - 96);
        else if (j < 160) src = g_T1f + n * NCOL + 128 + b * 32 + (j - 128);
        else              src = g_T2f + n * NCOL + 128 + b * 32 + (j - 160);
        *(float4*)&sf[r][j] = *(const float4*)src;
    }
    __syncthreads();

    int c = tid;
    float acc[16];
#pragma unroll
    for (int r = 0; r < 16; r++) acc[r] = 0.f;

#pragma unroll 4
    for (int q = 0; q < 48; q++) {
        int j = q * 4;
        float w0 = g_W[(j + 0) * 128 + c];
        float w1 = g_W[(j + 1) * 128 + c];
        float w2 = g_W[(j + 2) * 128 + c];
        float w3 = g_W[(j + 3) * 128 + c];
#pragma unroll
        for (int r = 0; r < 16; r++) {
            float4 f = *(const float4*)&sf[r][j];
            acc[r] = fmaf(f.x, w0, fmaf(f.y, w1, fmaf(f.z, w2, fmaf(f.w, w3, acc[r]))));
        }
    }
    float bias = g_bias[c];
#pragma unroll
    for (int r = 0; r < 16; r++) pre[r][c] = acc[r] + bias;
    __syncthreads();

#pragma unroll
    for (int q = 0; q < 4; q++) {
        int item = tid + q * 128;
        int r = item >> 5, f = item & 31;
        int n = n0 + r;
        int gidx = (b * NN + n) * 32 + f;
        float cv = C[gidx];
        float pi = pre[r][f];
        float pf = pre[r][32 + f];
        float pc = pre[r][64 + f];
        float po = pre[r][96 + f];
        float I  = 1.f / (1.f + expf(-(pi + w_ci[f] * cv)));
        float F  = 1.f / (1.f + expf(-(pf + w_cf[f] * cv)));
        float T  = tanhf(pc);
        float cn = F * cv + I * T;
        float O  = 1.f / (1.f + expf(-(po + w_co[f] * cn)));
        Hout[gidx] = O * tanhf(cn);
        Cout[gidx] = cn;
    }
}

// ---------------- launch ----------------
extern "C" void kernel_launch(void* const* d_in, const int* in_sizes, int n_in,
                              void* d_out, int out_size)
{
    const float* X   = (const float*)d_in[0];
    const float* L   = (const float*)d_in[1];
    const float* H   = (const float*)d_in[2];
    const float* C   = (const float*)d_in[3];
    const float* Wxi = (const float*)d_in[4];
    const float* bxi = (const float*)d_in[5];
    const float* Whi = (const float*)d_in[6];
    const float* bhi = (const float*)d_in[7];
    const float* Wxf = (const float*)d_in[8];
    const float* bxf = (const float*)d_in[9];
    const float* Whf = (const float*)d_in[10];
    const float* bhf = (const float*)d_in[11];
    const float* Wxc = (const float*)d_in[12];
    const float* bxc = (const float*)d_in[13];
    const float* Whc = (const float*)d_in[14];
    const float* bhc = (const float*)d_in[15];
    const float* Wxo = (const float*)d_in[16];
    const float* bxo = (const float*)d_in[17];
    const float* Who = (const float*)d_in[18];
    const float* bho = (const float*)d_in[19];
    const float* w_ci = (const float*)d_in[20];
    const float* w_cf = (const float*)d_in[21];
    const float* w_co = (const float*)d_in[22];
    const float* b_i = (const float*)d_in[23];
    const float* b_f = (const float*)d_in[24];
    const float* b_c = (const float*)d_in[25];
    const float* b_o = (const float*)d_in[26];

    float* Hout = (float*)d_out;
    float* Cout = Hout + NB * NN * CF;

    static int smem_set = 0;
    if (!smem_set) {
        cudaFuncSetAttribute(mma_gemm, cudaFuncAttributeMaxDynamicSharedMemorySize,
                             GEMM_SMEM);
        smem_set = 1;
    }

    prep_kernel<<<1, 256>>>(Wxi, Whi, Wxf, Whf, Wxc, Whc, Wxo, Who,
                            bxi, bhi, bxf, bhf, bxc, bhc, bxo, bho,
                            b_i, b_f, b_c, b_o);
    splitL_kernel<<<NN * NN / 4 / 256, 256>>>((const float4*)L);
    pack_kernel<<<(NN * NCOL / 4) / 256, 256>>>(X, H);

    dim3 ggrid(NCOL / GN, NN / GM);     // (4, 32) = 128 CTAs, one wave

    splitB_kernel<<<(NN * NCOL / 4) / 256, 256>>>(0);
    mma_gemm<<<ggrid, 256, GEMM_SMEM>>>(0);
    splitB_kernel<<<(NN * NCOL / 4) / 256, 256>>>(1);
    mma_gemm<<<ggrid, 256, GEMM_SMEM>>>(1);

    gates_kernel<<<BPN / 16, 128>>>(X, H, C, w_ci, w_cf, w_co, Hout, Cout);
}

// round 11
// speedup vs baseline: 3.2606x; 1.5242x over previous
#include <cuda_runtime.h>
#include <cuda_fp16.h>
#include <cstdint>
#include <math.h>

// Problem constants
#define NB   4
#define NN   4096
#define CF   32
#define NCOL 256          // combined columns: 128 (X) + 128 (H), each b*32+f
#define BPN  (NB*NN)

// GEMM tiling
#define GM 128
#define GN 64
#define KC 64              // k-elements per chunk (128 B per fp16 row)
#define NCHUNK (NN / KC)   // 64
#define STAGES 4
#define A_TILE 16384       // 128 rows * 128 B
#define B_TILE 8192        // 64 rows * 128 B
#define STAGE_BYTES (2*A_TILE + B_TILE)            // 40960
#define GEMM_SMEM (STAGES * STAGE_BYTES)           // 163840

#define SWZ(x) ((x) ^ (((x) >> 3) & 0x70))

// ---------------- device scratch (allocation-free rule) ----------------
__device__ __half g_Lhi[(size_t)NN*NN];     // fp16 hi of L
__device__ __half g_Llo[(size_t)NN*NN];     // fp16 residual of L
__device__ __half g_B0 [(size_t)NN*NCOL];   // fp16 of R   (pass-0 B operand)
__device__ __half g_B1 [(size_t)NN*NCOL];   // fp16 of T1  (pass-1 B operand)
__device__ float g_Rf [NN*NCOL];
__device__ float g_T1f[NN*NCOL];
__device__ float g_T2f[NN*NCOL];
__device__ float g_W [192*128];
__device__ float g_bias[128];

// ---------------- low-level helpers ----------------
__device__ __forceinline__ uint32_t smem_u32(const void* p) {
    uint32_t a;
    asm("{ .reg .u64 t; cvta.to.shared.u64 t, %1; cvt.u32.u64 %0, t; }" : "=r"(a) : "l"(p));
    return a;
}
__device__ __forceinline__ void cp_async16(uint32_t saddr, const void* gptr) {
    asm volatile("cp.async.cg.shared.global [%0], [%1], 16;" :: "r"(saddr), "l"(gptr));
}
__device__ __forceinline__ void cp_commit() {
    asm volatile("cp.async.commit_group;" ::: "memory");
}

#define LDSM4(r, a) \
    asm volatile("ldmatrix.sync.aligned.m8n8.x4.shared.b16 {%0,%1,%2,%3}, [%4];" \
        : "=r"((r)[0]), "=r"((r)[1]), "=r"((r)[2]), "=r"((r)[3]) : "r"(a))
#define LDSM4T(r, a) \
    asm volatile("ldmatrix.sync.aligned.m8n8.x4.trans.shared.b16 {%0,%1,%2,%3}, [%4];" \
        : "=r"((r)[0]), "=r"((r)[1]), "=r"((r)[2]), "=r"((r)[3]) : "r"(a))
#define MMA(c, a, b) \
    asm volatile("mma.sync.aligned.m16n8k16.row.col.f32.f16.f16.f32 " \
        "{%0,%1,%2,%3}, {%4,%5,%6,%7}, {%8,%9}, {%0,%1,%2,%3};" \
        : "+f"((c)[0]), "+f"((c)[1]), "+f"((c)[2]), "+f"((c)[3]) \
        : "r"((a)[0]), "r"((a)[1]), "r"((a)[2]), "r"((a)[3]), \
          "r"((b)[0]), "r"((b)[1]))

__device__ __forceinline__ float fast_sigmoid(float x) {
    return 1.f / (1.f + __expf(-x));
}
__device__ __forceinline__ float fast_tanh(float x) {
    float e = __expf(2.f * x);
    return (e - 1.f) / (e + 1.f);
}

// ---------------- prep: combine weights & biases ----------------
__global__ void prep_kernel(
    const float* __restrict__ Wxi, const float* __restrict__ Whi,
    const float* __restrict__ Wxf, const float* __restrict__ Whf,
    const float* __restrict__ Wxc, const float* __restrict__ Whc,
    const float* __restrict__ Wxo, const float* __restrict__ Who,
    const float* __restrict__ bxi, const float* __restrict__ bhi,
    const float* __restrict__ bxf, const float* __restrict__ bhf,
    const float* __restrict__ bxc, const float* __restrict__ bhc,
    const float* __restrict__ bxo, const float* __restrict__ bho,
    const float* __restrict__ b_i, const float* __restrict__ b_f,
    const float* __restrict__ b_c, const float* __restrict__ b_o)
{
    const float* Wx[4] = {Wxi, Wxf, Wxc, Wxo};
    const float* Wh[4] = {Whi, Whf, Whc, Who};
    const float* bx[4] = {bxi, bxf, bxc, bxo};
    const float* bh[4] = {bhi, bhf, bhc, bho};
    const float* bg[4] = {b_i, b_f, b_c, b_o};

    int idx = blockIdx.x * blockDim.x + threadIdx.x;
    if (idx < 192 * 128) {
        int j = idx >> 7, c = idx & 127;
        int part = j >> 5, r = j & 31;
        int gate = c >> 5, co = c & 31;
        float v;
        if (part < 3) v = Wx[gate][part * 1024 + r * 32 + co];
        else          v = Wh[gate][(part - 3) * 1024 + r * 32 + co];
        g_W[idx] = v;
    }
    if (blockIdx.x == 0 && threadIdx.x < 128) {
        int c = threadIdx.x;
        int gate = c >> 5, co = c & 31;
        g_bias[c] = bx[gate][co] + bh[gate][co] + bg[gate][co];
    }
}

// ---------------- split L (fp32 -> fp16 hi + fp16 residual) --------------
__global__ void __launch_bounds__(256)
splitL_kernel(const float4* __restrict__ L4)
{
    int idx = blockIdx.x * blockDim.x + threadIdx.x;
    float4 v = L4[idx];
    __half h0 = __float2half_rn(v.x);
    __half h1 = __float2half_rn(v.y);
    __half h2 = __float2half_rn(v.z);
    __half h3 = __float2half_rn(v.w);
    __half l0 = __float2half_rn(v.x - __half2float(h0));
    __half l1 = __float2half_rn(v.y - __half2float(h1));
    __half l2 = __float2half_rn(v.z - __half2float(h2));
    __half l3 = __float2half_rn(v.w - __half2float(h3));
    __half2* H2 = (__half2*)g_Lhi;
    __half2* L2 = (__half2*)g_Llo;
    H2[2*idx]   = __halves2half2(h0, h1);
    H2[2*idx+1] = __halves2half2(h2, h3);
    L2[2*idx]   = __halves2half2(l0, l1);
    L2[2*idx+1] = __halves2half2(l2, l3);
}

// ------- pack R = [X | H] into fp32 [NN,256] + fp16 B0 -------------------
__global__ void pack_kernel(const float* __restrict__ X, const float* __restrict__ H)
{
    int idx = blockIdx.x * blockDim.x + threadIdx.x;   // float4 index
    int m  = idx >> 6;
    int c4 = (idx & 63) << 2;
    const float* src;
    if (c4 < 128) {
        int b = c4 >> 5, f = c4 & 31;
        src = X + (b * NN + m) * 32 + f;
    } else {
        int cc = c4 - 128;
        int b = cc >> 5, f = cc & 31;
        src = H + (b * NN + m) * 32 + f;
    }
    float4 v = *(const float4*)src;
    ((float4*)g_Rf)[idx] = v;
    __half2* B2 = (__half2*)g_B0;
    B2[2*idx]   = __halves2half2(__float2half_rn(v.x), __float2half_rn(v.y));
    B2[2*idx+1] = __halves2half2(__float2half_rn(v.z), __float2half_rn(v.w));
}

// ---------------- HMMA GEMM: D = L @ B (2-product fp16 split A) ----------
__device__ __forceinline__ void issue_stage(uint32_t stb, int ck, int rowBase,
                                            int colBase, int tid,
                                            const __half* __restrict__ Bp)
{
    const char* Lh = (const char*)g_Lhi;
    const char* Ll = (const char*)g_Llo;
    size_t ka = (size_t)ck * 128;              // byte offset along K in L rows
#pragma unroll
    for (int i = 0; i < 4; i++) {
        int g = tid + i * 256;
        int r = g >> 3, cb = (g & 7) << 4;     // A: 128 rows x 8x16B
        uint32_t d = SWZ((uint32_t)(r * 128 + cb));
        size_t so = (size_t)(rowBase + r) * 8192 + ka + cb;
        cp_async16(stb + d,          Lh + so);
        cp_async16(stb + A_TILE + d, Ll + so);
    }
#pragma unroll
    for (int i = 0; i < 2; i++) {
        int g = tid + i * 256;
        int r = g >> 3, cb = (g & 7) << 4;     // B: 64 k-rows x 8x16B
        uint32_t d = SWZ((uint32_t)(r * 128 + cb));
        size_t so = (size_t)(ck * KC + r) * 512 + (size_t)colBase * 2 + cb;
        cp_async16(stb + 2*A_TILE + d, (const char*)Bp + so);
    }
}

__global__ void __launch_bounds__(256, 1)
mma_gemm(int pass)
{
    extern __shared__ __align__(1024) char smem[];
    uint32_t sb = smem_u32(smem);
    int tid  = threadIdx.x;
    int lane = tid & 31, wid = tid >> 5;
    int wm = wid & 3;          // M quadrant (rows wm*32)
    int wn = wid >> 2;         // N half (cols wn*32)
    int rowBase = blockIdx.y * GM;
    int colBase = blockIdx.x * GN;
    const __half* Bp = pass ? g_B1 : g_B0;

    int laneRow  = lane & 15;
    int laneHalf = (lane >> 4) << 4;

    float acc[2][4][4];
#pragma unroll
    for (int a = 0; a < 2; a++)
#pragma unroll
        for (int b = 0; b < 4; b++)
#pragma unroll
            for (int c = 0; c < 4; c++) acc[a][b][c] = 0.f;

    // prologue: stages 0..2
    issue_stage(sb + 0 * STAGE_BYTES, 0, rowBase, colBase, tid, Bp);
    cp_commit();
    issue_stage(sb + 1 * STAGE_BYTES, 1, rowBase, colBase, tid, Bp);
    cp_commit();
    issue_stage(sb + 2 * STAGE_BYTES, 2, rowBase, colBase, tid, Bp);
    cp_commit();

    for (int ck = 0; ck < NCHUNK; ck++) {
        asm volatile("cp.async.wait_group 2;" ::: "memory");
        __syncthreads();

        if (ck + 3 < NCHUNK)
            issue_stage(sb + ((ck + 3) & 3) * STAGE_BYTES, ck + 3,
                        rowBase, colBase, tid, Bp);
        cp_commit();   // empty group in tail keeps wait_group accounting exact

        uint32_t stb = sb + (ck & 3) * STAGE_BYTES;
#pragma unroll
        for (int ks = 0; ks < 4; ks++) {
            uint32_t ah[2][4], al[2][4];
#pragma unroll
            for (int mt = 0; mt < 2; mt++) {
                uint32_t off = SWZ((uint32_t)((wm * 32 + mt * 16 + laneRow) * 128
                                              + ks * 32 + laneHalf));
                LDSM4(ah[mt], stb + off);
                LDSM4(al[mt], stb + A_TILE + off);
            }
            uint32_t bh[4][2];
#pragma unroll
            for (int nh = 0; nh < 2; nh++) {
                uint32_t off = SWZ((uint32_t)((ks * 16 + laneRow) * 128
                                              + wn * 64 + nh * 32 + laneHalf));
                uint32_t q[4];
                LDSM4T(q, stb + 2*A_TILE + off);
                bh[nh*2][0] = q[0]; bh[nh*2][1] = q[1];
                bh[nh*2+1][0] = q[2]; bh[nh*2+1][1] = q[3];
            }
#pragma unroll
            for (int mt = 0; mt < 2; mt++)
#pragma unroll
                for (int nt = 0; nt < 4; nt++) {
                    MMA(acc[mt][nt], ah[mt], bh[nt]);
                    MMA(acc[mt][nt], al[mt], bh[nt]);
                }
        }
    }

    // epilogue
    float* dst = pass ? g_T2f : g_T1f;
    int r0 = rowBase + wm * 32 + (lane >> 2);
    int c0 = colBase + wn * 32 + ((lane & 3) << 1);
#pragma unroll
    for (int mt = 0; mt < 2; mt++) {
#pragma unroll
        for (int nt = 0; nt < 4; nt++) {
            int rr = r0 + mt * 16;
            int cc = c0 + nt * 8;
            float2 vlo = make_float2(acc[mt][nt][0], acc[mt][nt][1]);
            float2 vhi = make_float2(acc[mt][nt][2], acc[mt][nt][3]);
            if (pass) {
                float2 s0 = *(const float2*)(g_Rf + (size_t)rr * NCOL + cc);
                float2 s1 = *(const float2*)(g_Rf + (size_t)(rr + 8) * NCOL + cc);
                vlo.x = 2.f * vlo.x - s0.x;  vlo.y = 2.f * vlo.y - s0.y;
                vhi.x = 2.f * vhi.x - s1.x;  vhi.y = 2.f * vhi.y - s1.y;
            }
            *(float2*)(dst + (size_t)rr * NCOL + cc)       = vlo;
            *(float2*)(dst + (size_t)(rr + 8) * NCOL + cc) = vhi;
            if (!pass) {   // produce pass-1 B operand (fp16 of T1) for free
                __half2* B2 = (__half2*)g_B1;
                B2[((size_t)rr * NCOL + cc) >> 1] =
                    __halves2half2(__float2half_rn(vlo.x), __float2half_rn(vlo.y));
                B2[((size_t)(rr + 8) * NCOL + cc) >> 1] =
                    __halves2half2(__float2half_rn(vhi.x), __float2half_rn(vhi.y));
            }
        }
    }
}

// ---------------- gate GEMM + fused LSTM pointwise ----------------
__global__ void __launch_bounds__(128)
gates_kernel(const float* __restrict__ X, const float* __restrict__ H,
             const float* __restrict__ C,
             const float* __restrict__ w_ci, const float* __restrict__ w_cf,
             const float* __restrict__ w_co,
             float* __restrict__ Hout, float* __restrict__ Cout)
{
    __shared__ float sf[16][192];
    __shared__ float pre[16][128];

    int tid  = threadIdx.x;
    int row0 = blockIdx.x * 16;
    int b    = row0 >> 12;
    int n0   = row0 & 4095;

#pragma unroll
    for (int it = 0; it < 6; it++) {
        int i = tid + it * 128;
        int r = i / 48;
        int j = (i % 48) * 4;
        int n = n0 + r;
        const float* src;
        if      (j < 32)  src = X     + (b * NN + n) * 32 + j;
        else if (j < 64)  src = g_T1f + n * NCOL + b * 32 + (j - 32);
        else if (j < 96)  src = g_T2f + n * NCOL + b * 32 + (j - 64);
        else if (j < 128) src = H     + (b * NN + n) * 32 + (j - 96);
        else if (j < 160) src = g_T1f + n * NCOL + 128 + b * 32 + (j - 128);
        else              src = g_T2f + n * NCOL + 128 + b * 32 + (j - 160);
        *(float4*)&sf[r][j] = *(const float4*)src;
    }
    __syncthreads();

    int c = tid;
    float acc[16];
#pragma unroll
    for (int r = 0; r < 16; r++) acc[r] = 0.f;

#pragma unroll 4
    for (int q = 0; q < 48; q++) {
        int j = q * 4;
        float w0 = g_W[(j + 0) * 128 + c];
        float w1 = g_W[(j + 1) * 128 + c];
        float w2 = g_W[(j + 2) * 128 + c];
        float w3 = g_W[(j + 3) * 128 + c];
#pragma unroll
        for (int r = 0; r < 16; r++) {
            float4 f = *(const float4*)&sf[r][j];
            acc[r] = fmaf(f.x, w0, fmaf(f.y, w1, fmaf(f.z, w2, fmaf(f.w, w3, acc[r]))));
        }
    }
    float bias = g_bias[c];
#pragma unroll
    for (int r = 0; r < 16; r++) pre[r][c] = acc[r] + bias;
    __syncthreads();

#pragma unroll
    for (int q = 0; q < 4; q++) {
        int item = tid + q * 128;
        int r = item >> 5, f = item & 31;
        int n = n0 + r;
        int gidx = (b * NN + n) * 32 + f;
        float cv = C[gidx];
        float pi = pre[r][f];
        float pf = pre[r][32 + f];
        float pc = pre[r][64 + f];
        float po = pre[r][96 + f];
        float I  = fast_sigmoid(pi + w_ci[f] * cv);
        float F  = fast_sigmoid(pf + w_cf[f] * cv);
        float T  = fast_tanh(pc);
        float cn = F * cv + I * T;
        float O  = fast_sigmoid(po + w_co[f] * cn);
        Hout[gidx] = O * fast_tanh(cn);
        Cout[gidx] = cn;
    }
}

// ---------------- launch ----------------
extern "C" void kernel_launch(void* const* d_in, const int* in_sizes, int n_in,
                              void* d_out, int out_size)
{
    const float* X   = (const float*)d_in[0];
    const float* L   = (const float*)d_in[1];
    const float* H   = (const float*)d_in[2];
    const float* C   = (const float*)d_in[3];
    const float* Wxi = (const float*)d_in[4];
    const float* bxi = (const float*)d_in[5];
    const float* Whi = (const float*)d_in[6];
    const float* bhi = (const float*)d_in[7];
    const float* Wxf = (const float*)d_in[8];
    const float* bxf = (const float*)d_in[9];
    const float* Whf = (const float*)d_in[10];
    const float* bhf = (const float*)d_in[11];
    const float* Wxc = (const float*)d_in[12];
    const float* bxc = (const float*)d_in[13];
    const float* Whc = (const float*)d_in[14];
    const float* bhc = (const float*)d_in[15];
    const float* Wxo = (const float*)d_in[16];
    const float* bxo = (const float*)d_in[17];
    const float* Who = (const float*)d_in[18];
    const float* bho = (const float*)d_in[19];
    const float* w_ci = (const float*)d_in[20];
    const float* w_cf = (const float*)d_in[21];
    const float* w_co = (const float*)d_in[22];
    const float* b_i = (const float*)d_in[23];
    const float* b_f = (const float*)d_in[24];
    const float* b_c = (const float*)d_in[25];
    const float* b_o = (const float*)d_in[26];

    float* Hout = (float*)d_out;
    float* Cout = Hout + NB * NN * CF;

    static int smem_set = 0;
    if (!smem_set) {
        cudaFuncSetAttribute(mma_gemm, cudaFuncAttributeMaxDynamicSharedMemorySize,
                             GEMM_SMEM);
        smem_set = 1;
    }

    prep_kernel<<<96, 256>>>(Wxi, Whi, Wxf, Whf, Wxc, Whc, Wxo, Who,
                             bxi, bhi, bxf, bhf, bxc, bhc, bxo, bho,
                             b_i, b_f, b_c, b_o);
    splitL_kernel<<<NN * NN / 4 / 256, 256>>>((const float4*)L);
    pack_kernel<<<(NN * NCOL / 4) / 256, 256>>>(X, H);

    dim3 ggrid(NCOL / GN, NN / GM);     // (4, 32) = 128 CTAs, one wave

    mma_gemm<<<ggrid, 256, GEMM_SMEM>>>(0);
    mma_gemm<<<ggrid, 256, GEMM_SMEM>>>(1);

    gates_kernel<<<BPN / 16, 128>>>(X, H, C, w_ci, w_cf, w_co, Hout, Cout);
}

// round 13
// speedup vs baseline: 3.2648x; 1.0013x over previous
#include <cuda_runtime.h>
#include <cuda_fp16.h>
#include <cstdint>
#include <math.h>

// Problem constants
#define NB   4
#define NN   4096
#define CF   32
#define NCOL 256          // combined columns: 128 (X) + 128 (H), each b*32+f
#define BPN  (NB*NN)

// GEMM tiling
#define GM 128
#define GN 64
#define KC 64              // k-elements per chunk (128 B per fp16 row)
#define NCHUNK (NN / KC)   // 64
#define STAGES 4
#define A_TILE 16384       // 128 rows * 128 B
#define B_TILE 8192        // 64 rows * 128 B
#define STAGE_BYTES (2*A_TILE + B_TILE)            // 40960
#define GEMM_SMEM (STAGES * STAGE_BYTES)           // 163840

#define SWZ(x) ((x) ^ (((x) >> 3) & 0x70))

// ---------------- device scratch (allocation-free rule) ----------------
__device__ __half g_Lhi[(size_t)NN*NN];     // fp16 hi of L
__device__ __half g_Llo[(size_t)NN*NN];     // fp16 residual of L
__device__ __half g_B0 [(size_t)NN*NCOL];   // fp16 of R   (pass-0 B operand)
__device__ __half g_B1 [(size_t)NN*NCOL];   // fp16 of T1  (pass-1 B operand)
__device__ float g_Rf [NN*NCOL];
__device__ float g_T1f[NN*NCOL];
__device__ float g_T2f[NN*NCOL];
__device__ float g_W [192*128];
__device__ float g_bias[128];

// ---------------- low-level helpers ----------------
__device__ __forceinline__ uint32_t smem_u32(const void* p) {
    uint32_t a;
    asm("{ .reg .u64 t; cvta.to.shared.u64 t, %1; cvt.u32.u64 %0, t; }" : "=r"(a) : "l"(p));
    return a;
}
__device__ __forceinline__ void cp_async16(uint32_t saddr, const void* gptr) {
    asm volatile("cp.async.cg.shared.global [%0], [%1], 16;" :: "r"(saddr), "l"(gptr));
}
__device__ __forceinline__ void cp_commit() {
    asm volatile("cp.async.commit_group;" ::: "memory");
}

#define LDSM4(r, a) \
    asm volatile("ldmatrix.sync.aligned.m8n8.x4.shared.b16 {%0,%1,%2,%3}, [%4];" \
        : "=r"((r)[0]), "=r"((r)[1]), "=r"((r)[2]), "=r"((r)[3]) : "r"(a))
#define LDSM4T(r, a) \
    asm volatile("ldmatrix.sync.aligned.m8n8.x4.trans.shared.b16 {%0,%1,%2,%3}, [%4];" \
        : "=r"((r)[0]), "=r"((r)[1]), "=r"((r)[2]), "=r"((r)[3]) : "r"(a))
#define MMA(c, a, b) \
    asm volatile("mma.sync.aligned.m16n8k16.row.col.f32.f16.f16.f32 " \
        "{%0,%1,%2,%3}, {%4,%5,%6,%7}, {%8,%9}, {%0,%1,%2,%3};" \
        : "+f"((c)[0]), "+f"((c)[1]), "+f"((c)[2]), "+f"((c)[3]) \
        : "r"((a)[0]), "r"((a)[1]), "r"((a)[2]), "r"((a)[3]), \
          "r"((b)[0]), "r"((b)[1]))

__device__ __forceinline__ float fast_sigmoid(float x) {
    return 1.f / (1.f + __expf(-x));
}
__device__ __forceinline__ float fast_tanh(float x) {
    float e = __expf(2.f * x);
    return (e - 1.f) / (e + 1.f);
}

// ---------------- prep: combine weights & biases ----------------
__global__ void prep_kernel(
    const float* __restrict__ Wxi, const float* __restrict__ Whi,
    const float* __restrict__ Wxf, const float* __restrict__ Whf,
    const float* __restrict__ Wxc, const float* __restrict__ Whc,
    const float* __restrict__ Wxo, const float* __restrict__ Who,
    const float* __restrict__ bxi, const float* __restrict__ bhi,
    const float* __restrict__ bxf, const float* __restrict__ bhf,
    const float* __restrict__ bxc, const float* __restrict__ bhc,
    const float* __restrict__ bxo, const float* __restrict__ bho,
    const float* __restrict__ b_i, const float* __restrict__ b_f,
    const float* __restrict__ b_c, const float* __restrict__ b_o)
{
    const float* Wx[4] = {Wxi, Wxf, Wxc, Wxo};
    const float* Wh[4] = {Whi, Whf, Whc, Who};
    const float* bx[4] = {bxi, bxf, bxc, bxo};
    const float* bh[4] = {bhi, bhf, bhc, bho};
    const float* bg[4] = {b_i, b_f, b_c, b_o};

    int idx = blockIdx.x * blockDim.x + threadIdx.x;
    if (idx < 192 * 128) {
        int j = idx >> 7, c = idx & 127;
        int part = j >> 5, r = j & 31;
        int gate = c >> 5, co = c & 31;
        float v;
        if (part < 3) v = Wx[gate][part * 1024 + r * 32 + co];
        else          v = Wh[gate][(part - 3) * 1024 + r * 32 + co];
        g_W[idx] = v;
    }
    if (blockIdx.x == 0 && threadIdx.x < 128) {
        int c = threadIdx.x;
        int gate = c >> 5, co = c & 31;
        g_bias[c] = bx[gate][co] + bh[gate][co] + bg[gate][co];
    }
}

// ---------------- split L (fp32 -> fp16 hi + fp16 residual) --------------
__global__ void __launch_bounds__(256)
splitL_kernel(const float4* __restrict__ L4)
{
    int idx = blockIdx.x * blockDim.x + threadIdx.x;
    float4 v = L4[idx];
    __half h0 = __float2half_rn(v.x);
    __half h1 = __float2half_rn(v.y);
    __half h2 = __float2half_rn(v.z);
    __half h3 = __float2half_rn(v.w);
    __half l0 = __float2half_rn(v.x - __half2float(h0));
    __half l1 = __float2half_rn(v.y - __half2float(h1));
    __half l2 = __float2half_rn(v.z - __half2float(h2));
    __half l3 = __float2half_rn(v.w - __half2float(h3));
    __half2* H2 = (__half2*)g_Lhi;
    __half2* L2 = (__half2*)g_Llo;
    H2[2*idx]   = __halves2half2(h0, h1);
    H2[2*idx+1] = __halves2half2(h2, h3);
    L2[2*idx]   = __halves2half2(l0, l1);
    L2[2*idx+1] = __halves2half2(l2, l3);
}

// ------- pack R = [X | H] into fp32 [NN,256] + fp16 B0 -------------------
__global__ void pack_kernel(const float* __restrict__ X, const float* __restrict__ H)
{
    int idx = blockIdx.x * blockDim.x + threadIdx.x;   // float4 index
    int m  = idx >> 6;
    int c4 = (idx & 63) << 2;
    const float* src;
    if (c4 < 128) {
        int b = c4 >> 5, f = c4 & 31;
        src = X + (b * NN + m) * 32 + f;
    } else {
        int cc = c4 - 128;
        int b = cc >> 5, f = cc & 31;
        src = H + (b * NN + m) * 32 + f;
    }
    float4 v = *(const float4*)src;
    ((float4*)g_Rf)[idx] = v;
    __half2* B2 = (__half2*)g_B0;
    B2[2*idx]   = __halves2half2(__float2half_rn(v.x), __float2half_rn(v.y));
    B2[2*idx+1] = __halves2half2(__float2half_rn(v.z), __float2half_rn(v.w));
}

// ---------------- HMMA GEMM: D = L @ B (2-product fp16 split A) ----------
__device__ __forceinline__ void issue_stage(uint32_t stb, int ck, int rowBase,
                                            int colBase, int tid,
                                            const __half* __restrict__ Bp)
{
    const char* Lh = (const char*)g_Lhi;
    const char* Ll = (const char*)g_Llo;
    size_t ka = (size_t)ck * 128;              // byte offset along K in L rows
#pragma unroll
    for (int i = 0; i < 4; i++) {
        int g = tid + i * 256;
        int r = g >> 3, cb = (g & 7) << 4;     // A: 128 rows x 8x16B
        uint32_t d = SWZ((uint32_t)(r * 128 + cb));
        size_t so = (size_t)(rowBase + r) * 8192 + ka + cb;
        cp_async16(stb + d,          Lh + so);
        cp_async16(stb + A_TILE + d, Ll + so);
    }
#pragma unroll
    for (int i = 0; i < 2; i++) {
        int g = tid + i * 256;
        int r = g >> 3, cb = (g & 7) << 4;     // B: 64 k-rows x 8x16B
        uint32_t d = SWZ((uint32_t)(r * 128 + cb));
        size_t so = (size_t)(ck * KC + r) * 512 + (size_t)colBase * 2 + cb;
        cp_async16(stb + 2*A_TILE + d, (const char*)Bp + so);
    }
}

__global__ void __launch_bounds__(256, 1)
mma_gemm(int pass)
{
    extern __shared__ __align__(1024) char smem[];
    uint32_t sb = smem_u32(smem);
    int tid  = threadIdx.x;
    int lane = tid & 31, wid = tid >> 5;
    int wm = wid & 3;          // M quadrant (rows wm*32)
    int wn = wid >> 2;         // N half (cols wn*32)
    int rowBase = blockIdx.y * GM;
    int colBase = blockIdx.x * GN;
    const __half* Bp = pass ? g_B1 : g_B0;

    int laneRow  = lane & 15;
    int laneHalf = (lane >> 4) << 4;

    float acc[2][4][4];
#pragma unroll
    for (int a = 0; a < 2; a++)
#pragma unroll
        for (int b = 0; b < 4; b++)
#pragma unroll
            for (int c = 0; c < 4; c++) acc[a][b][c] = 0.f;

    // double-buffered fragments (software pipeline over ks)
    uint32_t ah[2][2][4], al[2][2][4], bh[2][4][2];

    // prologue: stages 0..2
    issue_stage(sb + 0 * STAGE_BYTES, 0, rowBase, colBase, tid, Bp);
    cp_commit();
    issue_stage(sb + 1 * STAGE_BYTES, 1, rowBase, colBase, tid, Bp);
    cp_commit();
    issue_stage(sb + 2 * STAGE_BYTES, 2, rowBase, colBase, tid, Bp);
    cp_commit();

    for (int ck = 0; ck < NCHUNK; ck++) {
        asm volatile("cp.async.wait_group 2;" ::: "memory");
        __syncthreads();

        if (ck + 3 < NCHUNK)
            issue_stage(sb + ((ck + 3) & 3) * STAGE_BYTES, ck + 3,
                        rowBase, colBase, tid, Bp);
        cp_commit();   // empty group in tail keeps wait_group accounting exact

        uint32_t stb = sb + (ck & 3) * STAGE_BYTES;

        // load ks=0 fragments into buffer 0
#pragma unroll
        for (int mt = 0; mt < 2; mt++) {
            uint32_t off = SWZ((uint32_t)((wm * 32 + mt * 16 + laneRow) * 128
                                          + laneHalf));
            LDSM4(ah[0][mt], stb + off);
            LDSM4(al[0][mt], stb + A_TILE + off);
        }
#pragma unroll
        for (int nh = 0; nh < 2; nh++) {
            uint32_t off = SWZ((uint32_t)(laneRow * 128
                                          + wn * 64 + nh * 32 + laneHalf));
            uint32_t q[4];
            LDSM4T(q, stb + 2*A_TILE + off);
            bh[0][nh*2][0] = q[0];   bh[0][nh*2][1] = q[1];
            bh[0][nh*2+1][0] = q[2]; bh[0][nh*2+1][1] = q[3];
        }

#pragma unroll
        for (int ks = 0; ks < 4; ks++) {
            int cur = ks & 1, nxt = cur ^ 1;
            if (ks < 3) {
                // prefetch ks+1 fragments while MMAs below run
#pragma unroll
                for (int mt = 0; mt < 2; mt++) {
                    uint32_t off = SWZ((uint32_t)((wm * 32 + mt * 16 + laneRow) * 128
                                                  + (ks + 1) * 32 + laneHalf));
                    LDSM4(ah[nxt][mt], stb + off);
                    LDSM4(al[nxt][mt], stb + A_TILE + off);
                }
#pragma unroll
                for (int nh = 0; nh < 2; nh++) {
                    uint32_t off = SWZ((uint32_t)(((ks + 1) * 16 + laneRow) * 128
                                                  + wn * 64 + nh * 32 + laneHalf));
                    uint32_t q[4];
                    LDSM4T(q, stb + 2*A_TILE + off);
                    bh[nxt][nh*2][0] = q[0];   bh[nxt][nh*2][1] = q[1];
                    bh[nxt][nh*2+1][0] = q[2]; bh[nxt][nh*2+1][1] = q[3];
                }
            }
#pragma unroll
            for (int mt = 0; mt < 2; mt++)
#pragma unroll
                for (int nt = 0; nt < 4; nt++) {
                    MMA(acc[mt][nt], ah[cur][mt], bh[cur][nt]);
                    MMA(acc[mt][nt], al[cur][mt], bh[cur][nt]);
                }
        }
    }

    // epilogue
    float* dst = pass ? g_T2f : g_T1f;
    int r0 = rowBase + wm * 32 + (lane >> 2);
    int c0 = colBase + wn * 32 + ((lane & 3) << 1);
#pragma unroll
    for (int mt = 0; mt < 2; mt++) {
#pragma unroll
        for (int nt = 0; nt < 4; nt++) {
            int rr = r0 + mt * 16;
            int cc = c0 + nt * 8;
            float2 vlo = make_float2(acc[mt][nt][0], acc[mt][nt][1]);
            float2 vhi = make_float2(acc[mt][nt][2], acc[mt][nt][3]);
            if (pass) {
                float2 s0 = *(const float2*)(g_Rf + (size_t)rr * NCOL + cc);
                float2 s1 = *(const float2*)(g_Rf + (size_t)(rr + 8) * NCOL + cc);
                vlo.x = 2.f * vlo.x - s0.x;  vlo.y = 2.f * vlo.y - s0.y;
                vhi.x = 2.f * vhi.x - s1.x;  vhi.y = 2.f * vhi.y - s1.y;
            }
            *(float2*)(dst + (size_t)rr * NCOL + cc)       = vlo;
            *(float2*)(dst + (size_t)(rr + 8) * NCOL + cc) = vhi;
            if (!pass) {   // produce pass-1 B operand (fp16 of T1) for free
                __half2* B2 = (__half2*)g_B1;
                B2[((size_t)rr * NCOL + cc) >> 1] =
                    __halves2half2(__float2half_rn(vlo.x), __float2half_rn(vlo.y));
                B2[((size_t)(rr + 8) * NCOL + cc) >> 1] =
                    __halves2half2(__float2half_rn(vhi.x), __float2half_rn(vhi.y));
            }
        }
    }
}

// ---------------- gate GEMM + fused LSTM pointwise ----------------
__global__ void __launch_bounds__(128)
gates_kernel(const float* __restrict__ X, const float* __restrict__ H,
             const float* __restrict__ C,
             const float* __restrict__ w_ci, const float* __restrict__ w_cf,
             const float* __restrict__ w_co,
             float* __restrict__ Hout, float* __restrict__ Cout)
{
    __shared__ float sf[16][192];
    __shared__ float pre[16][128];

    int tid  = threadIdx.x;
    int row0 = blockIdx.x * 16;
    int b    = row0 >> 12;
    int n0   = row0 & 4095;

#pragma unroll
    for (int it = 0; it < 6; it++) {
        int i = tid + it * 128;
        int r = i / 48;
        int j = (i % 48) * 4;
        int n = n0 + r;
        const float* src;
        if      (j < 32)  src = X     + (b * NN + n) * 32 + j;
        else if (j < 64)  src = g_T1f + n * NCOL + b * 32 + (j - 32);
        else if (j < 96)  src = g_T2f + n * NCOL + b * 32 + (j - 64);
        else if (j < 128) src = H     + (b * NN + n) * 32 + (j - 96);
        else if (j < 160) src = g_T1f + n * NCOL + 128 + b * 32 + (j - 128);
        else              src = g_T2f + n * NCOL + 128 + b * 32 + (j - 160);
        *(float4*)&sf[r][j] = *(const float4*)src;
    }
    __syncthreads();

    int c = tid;
    float acc[16];
#pragma unroll
    for (int r = 0; r < 16; r++) acc[r] = 0.f;

#pragma unroll 4
    for (int q = 0; q < 48; q++) {
        int j = q * 4;
        float w0 = g_W[(j + 0) * 128 + c];
        float w1 = g_W[(j + 1) * 128 + c];
        float w2 = g_W[(j + 2) * 128 + c];
        float w3 = g_W[(j + 3) * 128 + c];
#pragma unroll
        for (int r = 0; r < 16; r++) {
            float4 f = *(const float4*)&sf[r][j];
            acc[r] = fmaf(f.x, w0, fmaf(f.y, w1, fmaf(f.z, w2, fmaf(f.w, w3, acc[r]))));
        }
    }
    float bias = g_bias[c];
#pragma unroll
    for (int r = 0; r < 16; r++) pre[r][c] = acc[r] + bias;
    __syncthreads();

#pragma unroll
    for (int q = 0; q < 4; q++) {
        int item = tid + q * 128;
        int r = item >> 5, f = item & 31;
        int n = n0 + r;
        int gidx = (b * NN + n) * 32 + f;
        float cv = C[gidx];
        float pi = pre[r][f];
        float pf = pre[r][32 + f];
        float pc = pre[r][64 + f];
        float po = pre[r][96 + f];
        float I  = fast_sigmoid(pi + w_ci[f] * cv);
        float F  = fast_sigmoid(pf + w_cf[f] * cv);
        float T  = fast_tanh(pc);
        float cn = F * cv + I * T;
        float O  = fast_sigmoid(po + w_co[f] * cn);
        Hout[gidx] = O * fast_tanh(cn);
        Cout[gidx] = cn;
    }
}

// ---------------- launch ----------------
extern "C" void kernel_launch(void* const* d_in, const int* in_sizes, int n_in,
                              void* d_out, int out_size)
{
    const float* X   = (const float*)d_in[0];
    const float* L   = (const float*)d_in[1];
    const float* H   = (const float*)d_in[2];
    const float* C   = (const float*)d_in[3];
    const float* Wxi = (const float*)d_in[4];
    const float* bxi = (const float*)d_in[5];
    const float* Whi = (const float*)d_in[6];
    const float* bhi = (const float*)d_in[7];
    const float* Wxf = (const float*)d_in[8];
    const float* bxf = (const float*)d_in[9];
    const float* Whf = (const float*)d_in[10];
    const float* bhf = (const float*)d_in[11];
    const float* Wxc = (const float*)d_in[12];
    const float* bxc = (const float*)d_in[13];
    const float* Whc = (const float*)d_in[14];
    const float* bhc = (const float*)d_in[15];
    const float* Wxo = (const float*)d_in[16];
    const float* bxo = (const float*)d_in[17];
    const float* Who = (const float*)d_in[18];
    const float* bho = (const float*)d_in[19];
    const float* w_ci = (const float*)d_in[20];
    const float* w_cf = (const float*)d_in[21];
    const float* w_co = (const float*)d_in[22];
    const float* b_i = (const float*)d_in[23];
    const float* b_f = (const float*)d_in[24];
    const float* b_c = (const float*)d_in[25];
    const float* b_o = (const float*)d_in[26];

    float* Hout = (float*)d_out;
    float* Cout = Hout + NB * NN * CF;

    static int smem_set = 0;
    if (!smem_set) {
        cudaFuncSetAttribute(mma_gemm, cudaFuncAttributeMaxDynamicSharedMemorySize,
                             GEMM_SMEM);
        smem_set = 1;
    }

    prep_kernel<<<96, 256>>>(Wxi, Whi, Wxf, Whf, Wxc, Whc, Wxo, Who,
                             bxi, bhi, bxf, bhf, bxc, bhc, bxo, bho,
                             b_i, b_f, b_c, b_o);
    splitL_kernel<<<NN * NN / 4 / 256, 256>>>((const float4*)L);
    pack_kernel<<<(NN * NCOL / 4) / 256, 256>>>(X, H);

    dim3 ggrid(NCOL / GN, NN / GM);     // (4, 32) = 128 CTAs, one wave

    mma_gemm<<<ggrid, 256, GEMM_SMEM>>>(0);
    mma_gemm<<<ggrid, 256, GEMM_SMEM>>>(1);

    gates_kernel<<<BPN / 16, 128>>>(X, H, C, w_ci, w_cf, w_co, Hout, Cout);
}

// round 16
// speedup vs baseline: 3.3078x; 1.0132x over previous
#include <cuda_runtime.h>
#include <cuda_fp16.h>
#include <cstdint>
#include <math.h>

// Problem constants
#define NB   4
#define NN   4096
#define CF   32
#define NCOL 256          // combined columns: 128 (X) + 128 (H), each b*32+f
#define BPN  (NB*NN)

// GEMM tiling: 64x64 CTA tile, 2 CTAs per SM
#define GM 64
#define GN 64
#define KC 64              // k-elements per chunk (128 B per fp16 row)
#define NCHUNK (NN / KC)   // 64
#define STAGES 4
#define A_TILE 8192        // 64 rows * 128 B
#define B_TILE 8192        // 64 k-rows * 128 B
#define STAGE_BYTES (2*A_TILE + B_TILE)            // 24576
#define GEMM_SMEM (STAGES * STAGE_BYTES)           // 98304

#define SWZ(x) ((x) ^ (((x) >> 3) & 0x70))

// ---------------- device scratch (allocation-free rule) ----------------
__device__ __half g_Lhi[(size_t)NN*NN];     // fp16 hi of L
__device__ __half g_Llo[(size_t)NN*NN];     // fp16 residual of L
__device__ __half g_B0 [(size_t)NN*NCOL];   // fp16 of R   (pass-0 B operand)
__device__ __half g_B1 [(size_t)NN*NCOL];   // fp16 of T1  (pass-1 B operand)
__device__ float g_Rf [NN*NCOL];
__device__ float g_T1f[NN*NCOL];
__device__ float g_T2f[NN*NCOL];
__device__ float g_W [192*128];
__device__ float g_bias[128];

// ---------------- low-level helpers ----------------
__device__ __forceinline__ uint32_t smem_u32(const void* p) {
    uint32_t a;
    asm("{ .reg .u64 t; cvta.to.shared.u64 t, %1; cvt.u32.u64 %0, t; }" : "=r"(a) : "l"(p));
    return a;
}
__device__ __forceinline__ void cp_async16(uint32_t saddr, const void* gptr) {
    asm volatile("cp.async.cg.shared.global [%0], [%1], 16;" :: "r"(saddr), "l"(gptr));
}
__device__ __forceinline__ void cp_commit() {
    asm volatile("cp.async.commit_group;" ::: "memory");
}

#define LDSM4(r, a) \
    asm volatile("ldmatrix.sync.aligned.m8n8.x4.shared.b16 {%0,%1,%2,%3}, [%4];" \
        : "=r"((r)[0]), "=r"((r)[1]), "=r"((r)[2]), "=r"((r)[3]) : "r"(a))
#define LDSM4T(r, a) \
    asm volatile("ldmatrix.sync.aligned.m8n8.x4.trans.shared.b16 {%0,%1,%2,%3}, [%4];" \
        : "=r"((r)[0]), "=r"((r)[1]), "=r"((r)[2]), "=r"((r)[3]) : "r"(a))
#define MMA(c, a, b) \
    asm volatile("mma.sync.aligned.m16n8k16.row.col.f32.f16.f16.f32 " \
        "{%0,%1,%2,%3}, {%4,%5,%6,%7}, {%8,%9}, {%0,%1,%2,%3};" \
        : "+f"((c)[0]), "+f"((c)[1]), "+f"((c)[2]), "+f"((c)[3]) \
        : "r"((a)[0]), "r"((a)[1]), "r"((a)[2]), "r"((a)[3]), \
          "r"((b)[0]), "r"((b)[1]))

__device__ __forceinline__ float fast_sigmoid(float x) {
    return 1.f / (1.f + __expf(-x));
}
__device__ __forceinline__ float fast_tanh(float x) {
    float e = __expf(2.f * x);
    return (e - 1.f) / (e + 1.f);
}

// ---------------- prep: combine weights & biases ----------------
__global__ void prep_kernel(
    const float* __restrict__ Wxi, const float* __restrict__ Whi,
    const float* __restrict__ Wxf, const float* __restrict__ Whf,
    const float* __restrict__ Wxc, const float* __restrict__ Whc,
    const float* __restrict__ Wxo, const float* __restrict__ Who,
    const float* __restrict__ bxi, const float* __restrict__ bhi,
    const float* __restrict__ bxf, const float* __restrict__ bhf,
    const float* __restrict__ bxc, const float* __restrict__ bhc,
    const float* __restrict__ bxo, const float* __restrict__ bho,
    const float* __restrict__ b_i, const float* __restrict__ b_f,
    const float* __restrict__ b_c, const float* __restrict__ b_o)
{
    const float* Wx[4] = {Wxi, Wxf, Wxc, Wxo};
    const float* Wh[4] = {Whi, Whf, Whc, Who};
    const float* bx[4] = {bxi, bxf, bxc, bxo};
    const float* bh[4] = {bhi, bhf, bhc, bho};
    const float* bg[4] = {b_i, b_f, b_c, b_o};

    int idx = blockIdx.x * blockDim.x + threadIdx.x;
    if (idx < 192 * 128) {
        int j = idx >> 7, c = idx & 127;
        int part = j >> 5, r = j & 31;
        int gate = c >> 5, co = c & 31;
        float v;
        if (part < 3) v = Wx[gate][part * 1024 + r * 32 + co];
        else          v = Wh[gate][(part - 3) * 1024 + r * 32 + co];
        g_W[idx] = v;
    }
    if (blockIdx.x == 0 && threadIdx.x < 128) {
        int c = threadIdx.x;
        int gate = c >> 5, co = c & 31;
        g_bias[c] = bx[gate][co] + bh[gate][co] + bg[gate][co];
    }
}

// ---------------- split L (fp32 -> fp16 hi + fp16 residual) --------------
__global__ void __launch_bounds__(256)
splitL_kernel(const float4* __restrict__ L4)
{
    int idx = blockIdx.x * blockDim.x + threadIdx.x;
    float4 v = L4[idx];
    __half h0 = __float2half_rn(v.x);
    __half h1 = __float2half_rn(v.y);
    __half h2 = __float2half_rn(v.z);
    __half h3 = __float2half_rn(v.w);
    __half l0 = __float2half_rn(v.x - __half2float(h0));
    __half l1 = __float2half_rn(v.y - __half2float(h1));
    __half l2 = __float2half_rn(v.z - __half2float(h2));
    __half l3 = __float2half_rn(v.w - __half2float(h3));
    __half2* H2 = (__half2*)g_Lhi;
    __half2* L2 = (__half2*)g_Llo;
    H2[2*idx]   = __halves2half2(h0, h1);
    H2[2*idx+1] = __halves2half2(h2, h3);
    L2[2*idx]   = __halves2half2(l0, l1);
    L2[2*idx+1] = __halves2half2(l2, l3);
}

// ------- pack R = [X | H] into fp32 [NN,256] + fp16 B0 -------------------
__global__ void pack_kernel(const float* __restrict__ X, const float* __restrict__ H)
{
    int idx = blockIdx.x * blockDim.x + threadIdx.x;   // float4 index
    int m  = idx >> 6;
    int c4 = (idx & 63) << 2;
    const float* src;
    if (c4 < 128) {
        int b = c4 >> 5, f = c4 & 31;
        src = X + (b * NN + m) * 32 + f;
    } else {
        int cc = c4 - 128;
        int b = cc >> 5, f = cc & 31;
        src = H + (b * NN + m) * 32 + f;
    }
    float4 v = *(const float4*)src;
    ((float4*)g_Rf)[idx] = v;
    __half2* B2 = (__half2*)g_B0;
    B2[2*idx]   = __halves2half2(__float2half_rn(v.x), __float2half_rn(v.y));
    B2[2*idx+1] = __halves2half2(__float2half_rn(v.z), __float2half_rn(v.w));
}

// ---------------- HMMA GEMM: D = L @ B (2-product fp16 split A) ----------
__device__ __forceinline__ void issue_stage(uint32_t stb, int ck, int rowBase,
                                            int colBase, int tid,
                                            const __half* __restrict__ Bp)
{
    const char* Lh = (const char*)g_Lhi;
    const char* Ll = (const char*)g_Llo;
    size_t ka = (size_t)ck * 128;              // byte offset along K in L rows
#pragma unroll
    for (int i = 0; i < 4; i++) {
        int g = tid + i * 128;
        int r = g >> 3, cb = (g & 7) << 4;     // A: 64 rows x 8x16B
        uint32_t d = SWZ((uint32_t)(r * 128 + cb));
        size_t so = (size_t)(rowBase + r) * 8192 + ka + cb;
        cp_async16(stb + d,          Lh + so);
        cp_async16(stb + A_TILE + d, Ll + so);
    }
#pragma unroll
    for (int i = 0; i < 4; i++) {
        int g = tid + i * 128;
        int r = g >> 3, cb = (g & 7) << 4;     // B: 64 k-rows x 8x16B
        uint32_t d = SWZ((uint32_t)(r * 128 + cb));
        size_t so = (size_t)(ck * KC + r) * 512 + (size_t)colBase * 2 + cb;
        cp_async16(stb + 2*A_TILE + d, (const char*)Bp + so);
    }
}

__global__ void __launch_bounds__(128, 2)
mma_gemm(int pass)
{
    extern __shared__ __align__(1024) char smem[];
    uint32_t sb = smem_u32(smem);
    int tid  = threadIdx.x;
    int lane = tid & 31, wid = tid >> 5;
    int wm = wid & 1;          // M half (rows wm*32)
    int wn = wid >> 1;         // N half (cols wn*32)
    int rowBase = blockIdx.y * GM;
    int colBase = blockIdx.x * GN;
    const __half* Bp = pass ? g_B1 : g_B0;

    int laneRow  = lane & 15;
    int laneHalf = (lane >> 4) << 4;

    float acc[2][4][4];
#pragma unroll
    for (int a = 0; a < 2; a++)
#pragma unroll
        for (int b = 0; b < 4; b++)
#pragma unroll
            for (int c = 0; c < 4; c++) acc[a][b][c] = 0.f;

    // double-buffered fragments (software pipeline over ks)
    uint32_t ah[2][2][4], al[2][2][4], bh[2][4][2];

    // prologue: stages 0..2
    issue_stage(sb + 0 * STAGE_BYTES, 0, rowBase, colBase, tid, Bp);
    cp_commit();
    issue_stage(sb + 1 * STAGE_BYTES, 1, rowBase, colBase, tid, Bp);
    cp_commit();
    issue_stage(sb + 2 * STAGE_BYTES, 2, rowBase, colBase, tid, Bp);
    cp_commit();

    for (int ck = 0; ck < NCHUNK; ck++) {
        asm volatile("cp.async.wait_group 2;" ::: "memory");
        __syncthreads();

        if (ck + 3 < NCHUNK)
            issue_stage(sb + ((ck + 3) & 3) * STAGE_BYTES, ck + 3,
                        rowBase, colBase, tid, Bp);
        cp_commit();   // empty group in tail keeps wait_group accounting exact

        uint32_t stb = sb + (ck & 3) * STAGE_BYTES;

        // load ks=0 fragments into buffer 0
#pragma unroll
        for (int mt = 0; mt < 2; mt++) {
            uint32_t off = SWZ((uint32_t)((wm * 32 + mt * 16 + laneRow) * 128
                                          + laneHalf));
            LDSM4(ah[0][mt], stb + off);
            LDSM4(al[0][mt], stb + A_TILE + off);
        }
#pragma unroll
        for (int nh = 0; nh < 2; nh++) {
            uint32_t off = SWZ((uint32_t)(laneRow * 128
                                          + wn * 64 + nh * 32 + laneHalf));
            uint32_t q[4];
            LDSM4T(q, stb + 2*A_TILE + off);
            bh[0][nh*2][0] = q[0];   bh[0][nh*2][1] = q[1];
            bh[0][nh*2+1][0] = q[2]; bh[0][nh*2+1][1] = q[3];
        }

#pragma unroll
        for (int ks = 0; ks < 4; ks++) {
            int cur = ks & 1, nxt = cur ^ 1;
            if (ks < 3) {
                // prefetch ks+1 fragments while MMAs below run
#pragma unroll
                for (int mt = 0; mt < 2; mt++) {
                    uint32_t off = SWZ((uint32_t)((wm * 32 + mt * 16 + laneRow) * 128
                                                  + (ks + 1) * 32 + laneHalf));
                    LDSM4(ah[nxt][mt], stb + off);
                    LDSM4(al[nxt][mt], stb + A_TILE + off);
                }
#pragma unroll
                for (int nh = 0; nh < 2; nh++) {
                    uint32_t off = SWZ((uint32_t)(((ks + 1) * 16 + laneRow) * 128
                                                  + wn * 64 + nh * 32 + laneHalf));
                    uint32_t q[4];
                    LDSM4T(q, stb + 2*A_TILE + off);
                    bh[nxt][nh*2][0] = q[0];   bh[nxt][nh*2][1] = q[1];
                    bh[nxt][nh*2+1][0] = q[2]; bh[nxt][nh*2+1][1] = q[3];
                }
            }
#pragma unroll
            for (int mt = 0; mt < 2; mt++)
#pragma unroll
                for (int nt = 0; nt < 4; nt++) {
                    MMA(acc[mt][nt], ah[cur][mt], bh[cur][nt]);
                    MMA(acc[mt][nt], al[cur][mt], bh[cur][nt]);
                }
        }
    }

    // epilogue
    float* dst = pass ? g_T2f : g_T1f;
    int r0 = rowBase + wm * 32 + (lane >> 2);
    int c0 = colBase + wn * 32 + ((lane & 3) << 1);
#pragma unroll
    for (int mt = 0; mt < 2; mt++) {
#pragma unroll
        for (int nt = 0; nt < 4; nt++) {
            int rr = r0 + mt * 16;
            int cc = c0 + nt * 8;
            float2 vlo = make_float2(acc[mt][nt][0], acc[mt][nt][1]);
            float2 vhi = make_float2(acc[mt][nt][2], acc[mt][nt][3]);
            if (pass) {
                float2 s0 = *(const float2*)(g_Rf + (size_t)rr * NCOL + cc);
                float2 s1 = *(const float2*)(g_Rf + (size_t)(rr + 8) * NCOL + cc);
                vlo.x = 2.f * vlo.x - s0.x;  vlo.y = 2.f * vlo.y - s0.y;
                vhi.x = 2.f * vhi.x - s1.x;  vhi.y = 2.f * vhi.y - s1.y;
            }
            *(float2*)(dst + (size_t)rr * NCOL + cc)       = vlo;
            *(float2*)(dst + (size_t)(rr + 8) * NCOL + cc) = vhi;
            if (!pass) {   // produce pass-1 B operand (fp16 of T1) for free
                __half2* B2 = (__half2*)g_B1;
                B2[((size_t)rr * NCOL + cc) >> 1] =
                    __halves2half2(__float2half_rn(vlo.x), __float2half_rn(vlo.y));
                B2[((size_t)(rr + 8) * NCOL + cc) >> 1] =
                    __halves2half2(__float2half_rn(vhi.x), __float2half_rn(vhi.y));
            }
        }
    }
}

// ---------------- gate GEMM + fused LSTM pointwise ----------------
__global__ void __launch_bounds__(128)
gates_kernel(const float* __restrict__ X, const float* __restrict__ H,
             const float* __restrict__ C,
             const float* __restrict__ w_ci, const float* __restrict__ w_cf,
             const float* __restrict__ w_co,
             float* __restrict__ Hout, float* __restrict__ Cout)
{
    __shared__ float sf[16][192];
    __shared__ float pre[16][128];

    int tid  = threadIdx.x;
    int row0 = blockIdx.x * 16;
    int b    = row0 >> 12;
    int n0   = row0 & 4095;

#pragma unroll
    for (int it = 0; it < 6; it++) {
        int i = tid + it * 128;
        int r = i / 48;
        int j = (i % 48) * 4;
        int n = n0 + r;
        const float* src;
        if      (j < 32)  src = X     + (b * NN + n) * 32 + j;
        else if (j < 64)  src = g_T1f + n * NCOL + b * 32 + (j - 32);
        else if (j < 96)  src = g_T2f + n * NCOL + b * 32 + (j - 64);
        else if (j < 128) src = H     + (b * NN + n) * 32 + (j - 96);
        else if (j < 160) src = g_T1f + n * NCOL + 128 + b * 32 + (j - 128);
        else              src = g_T2f + n * NCOL + 128 + b * 32 + (j - 160);
        *(float4*)&sf[r][j] = *(const float4*)src;
    }
    __syncthreads();

    int c = tid;
    float acc[16];
#pragma unroll
    for (int r = 0; r < 16; r++) acc[r] = 0.f;

#pragma unroll 4
    for (int q = 0; q < 48; q++) {
        int j = q * 4;
        float w0 = g_W[(j + 0) * 128 + c];
        float w1 = g_W[(j + 1) * 128 + c];
        float w2 = g_W[(j + 2) * 128 + c];
        float w3 = g_W[(j + 3) * 128 + c];
#pragma unroll
        for (int r = 0; r < 16; r++) {
            float4 f = *(const float4*)&sf[r][j];
            acc[r] = fmaf(f.x, w0, fmaf(f.y, w1, fmaf(f.z, w2, fmaf(f.w, w3, acc[r]))));
        }
    }
    float bias = g_bias[c];
#pragma unroll
    for (int r = 0; r < 16; r++) pre[r][c] = acc[r] + bias;
    __syncthreads();

#pragma unroll
    for (int q = 0; q < 4; q++) {
        int item = tid + q * 128;
        int r = item >> 5, f = item & 31;
        int n = n0 + r;
        int gidx = (b * NN + n) * 32 + f;
        float cv = C[gidx];
        float pi = pre[r][f];
        float pf = pre[r][32 + f];
        float pc = pre[r][64 + f];
        float po = pre[r][96 + f];
        float I  = fast_sigmoid(pi + w_ci[f] * cv);
        float F  = fast_sigmoid(pf + w_cf[f] * cv);
        float T  = fast_tanh(pc);
        float cn = F * cv + I * T;
        float O  = fast_sigmoid(po + w_co[f] * cn);
        Hout[gidx] = O * fast_tanh(cn);
        Cout[gidx] = cn;
    }
}

// ---------------- launch ----------------
extern "C" void kernel_launch(void* const* d_in, const int* in_sizes, int n_in,
                              void* d_out, int out_size)
{
    const float* X   = (const float*)d_in[0];
    const float* L   = (const float*)d_in[1];
    const float* H   = (const float*)d_in[2];
    const float* C   = (const float*)d_in[3];
    const float* Wxi = (const float*)d_in[4];
    const float* bxi = (const float*)d_in[5];
    const float* Whi = (const float*)d_in[6];
    const float* bhi = (const float*)d_in[7];
    const float* Wxf = (const float*)d_in[8];
    const float* bxf = (const float*)d_in[9];
    const float* Whf = (const float*)d_in[10];
    const float* bhf = (const float*)d_in[11];
    const float* Wxc = (const float*)d_in[12];
    const float* bxc = (const float*)d_in[13];
    const float* Whc = (const float*)d_in[14];
    const float* bhc = (const float*)d_in[15];
    const float* Wxo = (const float*)d_in[16];
    const float* bxo = (const float*)d_in[17];
    const float* Who = (const float*)d_in[18];
    const float* bho = (const float*)d_in[19];
    const float* w_ci = (const float*)d_in[20];
    const float* w_cf = (const float*)d_in[21];
    const float* w_co = (const float*)d_in[22];
    const float* b_i = (const float*)d_in[23];
    const float* b_f = (const float*)d_in[24];
    const float* b_c = (const float*)d_in[25];
    const float* b_o = (const float*)d_in[26];

    float* Hout = (float*)d_out;
    float* Cout = Hout + NB * NN * CF;

    static int smem_set = 0;
    if (!smem_set) {
        cudaFuncSetAttribute(mma_gemm, cudaFuncAttributeMaxDynamicSharedMemorySize,
                             GEMM_SMEM);
        smem_set = 1;
    }

    prep_kernel<<<96, 256>>>(Wxi, Whi, Wxf, Whf, Wxc, Whc, Wxo, Who,
                             bxi, bhi, bxf, bhf, bxc, bhc, bxo, bho,
                             b_i, b_f, b_c, b_o);
    splitL_kernel<<<NN * NN / 4 / 256, 256>>>((const float4*)L);
    pack_kernel<<<(NN * NCOL / 4) / 256, 256>>>(X, H);

    dim3 ggrid(NCOL / GN, NN / GM);     // (4, 64) = 256 CTAs, 2 per SM

    mma_gemm<<<ggrid, 128, GEMM_SMEM>>>(0);
    mma_gemm<<<ggrid, 128, GEMM_SMEM>>>(1);

    gates_kernel<<<BPN / 16, 128>>>(X, H, C, w_ci, w_cf, w_co, Hout, Cout);
}